// round 2
// baseline (speedup 1.0000x reference)
#include <cuda_runtime.h>
#include <math.h>

#define D_      100
#define DH_     50
#define B_      512
#define G_      3
#define NTAB    100000
#define DIN_    200
#define GSTRIDE 6348800      // 63488 * 100 floats per graph
#define STP     66           // padded row stride for transposed smem tiles
#define TILE    64
#define NTHR    160          // 20 col-threads x 8 row-threads

__device__ float g_bufA[G_ * 63488 * D_];
__device__ float g_bufB[G_ * 63488 * D_];

typedef unsigned long long ull;

__device__ __forceinline__ ull pk2(float lo, float hi) {
    ull r; asm("mov.b64 %0, {%1, %2};" : "=l"(r) : "f"(lo), "f"(hi)); return r;
}
__device__ __forceinline__ float2 upk2(ull v) {
    float2 f; asm("mov.b64 {%0, %1}, %2;" : "=f"(f.x), "=f"(f.y) : "l"(v)); return f;
}
#define FMA2(acc, a, b) asm("fma.rn.f32x2 %0, %1, %2, %0;" : "+l"(acc) : "l"(a), "l"(b))

// out[m][j] = relu( sum_k src(j)[k][m] * sW[k][j] + sB[j] ); src = X (j<50) else NB.
// sXT/sNT transposed tiles [100][STP].
__device__ __forceinline__ void gemm_relu_store(
    const float* sXT, const float* sNT, const float* sW, const float* sB,
    float* outRow0, int tid)
{
    const int ct = tid % 20, rt = tid / 20;
    const int j0 = ct * 5, mr = rt * 8;
    const float* aT = (j0 < DH_) ? sXT : sNT;
    ull acc[4][5];
#pragma unroll
    for (int c = 0; c < 5; c++) {
        float b = sB[j0 + c];
        ull bb = pk2(b, b);
        acc[0][c] = bb; acc[1][c] = bb; acc[2][c] = bb; acc[3][c] = bb;
    }
    const float* a0 = aT + mr;
#pragma unroll 2
    for (int k = 0; k < D_; k++) {
        const float* ak = a0 + k * STP;
        ull x0 = *(const ull*)(ak + 0);
        ull x1 = *(const ull*)(ak + 2);
        ull x2 = *(const ull*)(ak + 4);
        ull x3 = *(const ull*)(ak + 6);
        const float* wk = sW + k * D_ + j0;
#pragma unroll
        for (int c = 0; c < 5; c++) {
            float w = wk[c];
            ull wd = pk2(w, w);
            FMA2(acc[0][c], x0, wd);
            FMA2(acc[1][c], x1, wd);
            FMA2(acc[2][c], x2, wd);
            FMA2(acc[3][c], x3, wd);
        }
    }
#pragma unroll
    for (int r = 0; r < 4; r++) {
        float* o0 = outRow0 + (size_t)(mr + 2 * r) * D_ + j0;
        float* o1 = o0 + D_;
#pragma unroll
        for (int c = 0; c < 5; c++) {
            float2 v = upk2(acc[r][c]);
            o0[c] = fmaxf(v.x, 0.f);
            o1[c] = fmaxf(v.y, 0.f);
        }
    }
}

__device__ __forceinline__ void load_weights(
    const float* Ws, const float* Wn, const float* bs, const float* bn,
    float* sW, float* sB, int tid)
{
    for (int idx = tid; idx < D_ * DH_; idx += NTHR) {
        int i = idx / DH_, j = idx % DH_;
        sW[i * D_ + j]       = Ws[idx];
        sW[i * D_ + DH_ + j] = Wn[idx];
    }
    for (int j = tid; j < DH_; j += NTHR) {
        sB[j]       = bs[j];
        sB[DH_ + j] = bn[j];
    }
}

// ---------- pass 0: gathered from embedding table ----------
template<int S_>
__global__ __launch_bounds__(NTHR)
void pass0_kernel(const float* __restrict__ emb,
                  const int* __restrict__ xidx, int xstride,
                  const int* __restrict__ nidx, int nstride,
                  const float* __restrict__ Wself, const float* __restrict__ Wneigh,
                  const float* __restrict__ bself, const float* __restrict__ bneigh,
                  float* __restrict__ outbuf, int out_off)
{
    extern __shared__ float smem[];
    float* sXT = smem;                 // 100*STP
    float* sNT = smem + D_ * STP;      // 100*STP
    float* sW  = smem + 2 * D_ * STP;  // 100*100
    float* sB  = sW + D_ * D_;         // 100
    __shared__ int sXI[TILE];
    __shared__ int sNI[TILE * S_];

    const int tid  = threadIdx.x;
    const int g    = blockIdx.y;
    const int row0 = blockIdx.x * TILE;

    load_weights(Wself  + (size_t)(g * 4) * D_ * DH_,
                 Wneigh + (size_t)(g * 4) * D_ * DH_,
                 bself  + (size_t)(g * 4) * DH_,
                 bneigh + (size_t)(g * 4) * DH_, sW, sB, tid);

    const int* xg = xidx + (size_t)g * xstride;
    const int* ng = nidx + (size_t)g * nstride;
    if (tid < TILE) sXI[tid] = xg[row0 + tid];
    for (int i = tid; i < TILE * S_; i += NTHR) sNI[i] = ng[(size_t)row0 * S_ + i];
    __syncthreads();

    const float4* e4 = (const float4*)(emb + (size_t)g * NTAB * D_);

    for (int idx = tid; idx < TILE * 25; idx += NTHR) {
        int m = idx & 63, q = idx >> 6;
        float4 v = e4[(size_t)sXI[m] * 25 + q];
        int k = q * 4;
        sXT[(k + 0) * STP + m] = v.x;
        sXT[(k + 1) * STP + m] = v.y;
        sXT[(k + 2) * STP + m] = v.z;
        sXT[(k + 3) * STP + m] = v.w;
    }
    const float invS = 1.f / (float)S_;
    for (int idx = tid; idx < TILE * 25; idx += NTHR) {
        int m = idx & 63, q = idx >> 6;
        const int* np = &sNI[m * S_];
        float ax = 0.f, ay = 0.f, az = 0.f, aw = 0.f;
#pragma unroll
        for (int s = 0; s < S_; s++) {
            float4 v = e4[(size_t)np[s] * 25 + q];
            ax += v.x; ay += v.y; az += v.z; aw += v.w;
        }
        int k = q * 4;
        sNT[(k + 0) * STP + m] = ax * invS;
        sNT[(k + 1) * STP + m] = ay * invS;
        sNT[(k + 2) * STP + m] = az * invS;
        sNT[(k + 3) * STP + m] = aw * invS;
    }
    __syncthreads();

    float* outRow0 = outbuf + (size_t)g * GSTRIDE + (size_t)(out_off + row0) * D_;
    gemm_relu_store(sXT, sNT, sW, sB, outRow0, tid);
}

// ---------- passes 1..3: contiguous buffer inputs ----------
template<int S_>
__global__ __launch_bounds__(NTHR)
void passN_kernel(const float* __restrict__ inbuf, int x_off, int nb_off,
                  const float* __restrict__ Wself, const float* __restrict__ Wneigh,
                  const float* __restrict__ bself, const float* __restrict__ bneigh,
                  int l, float* __restrict__ outbuf, int out_off)
{
    extern __shared__ float smem[];
    float* sXT = smem;
    float* sNT = smem + D_ * STP;
    float* sW  = smem + 2 * D_ * STP;
    float* sB  = sW + D_ * D_;

    const int tid  = threadIdx.x;
    const int g    = blockIdx.y;
    const int row0 = blockIdx.x * TILE;

    load_weights(Wself  + (size_t)(g * 4 + l) * D_ * DH_,
                 Wneigh + (size_t)(g * 4 + l) * D_ * DH_,
                 bself  + (size_t)(g * 4 + l) * DH_,
                 bneigh + (size_t)(g * 4 + l) * DH_, sW, sB, tid);
    __syncthreads();

    const float* inG = inbuf + (size_t)g * GSTRIDE;

    for (int idx = tid; idx < TILE * 25; idx += NTHR) {
        int m = idx & 63, q = idx >> 6;
        float4 v = *(const float4*)(inG + (size_t)(x_off + row0 + m) * D_ + q * 4);
        int k = q * 4;
        sXT[(k + 0) * STP + m] = v.x;
        sXT[(k + 1) * STP + m] = v.y;
        sXT[(k + 2) * STP + m] = v.z;
        sXT[(k + 3) * STP + m] = v.w;
    }
    const float invS = 1.f / (float)S_;
    for (int idx = tid; idx < TILE * 25; idx += NTHR) {
        int m = idx & 63, q = idx >> 6;
        const float* p = inG + ((size_t)nb_off + (size_t)(row0 + m) * S_) * D_ + q * 4;
        float ax = 0.f, ay = 0.f, az = 0.f, aw = 0.f;
#pragma unroll
        for (int s = 0; s < S_; s++) {
            float4 v = *(const float4*)(p + (size_t)s * D_);
            ax += v.x; ay += v.y; az += v.z; aw += v.w;
        }
        int k = q * 4;
        sNT[(k + 0) * STP + m] = ax * invS;
        sNT[(k + 1) * STP + m] = ay * invS;
        sNT[(k + 2) * STP + m] = az * invS;
        sNT[(k + 3) * STP + m] = aw * invS;
    }
    __syncthreads();

    float* outRow0 = outbuf + (size_t)g * GSTRIDE + (size_t)(out_off + row0) * D_;
    gemm_relu_store(sXT, sNT, sW, sB, outRow0, tid);
}

// ---------- epilogue: FC + attention + reflect + final l2norm ----------
__device__ __forceinline__ float bsum128(float v, float* red, int tid) {
    __syncthreads();
#pragma unroll
    for (int o = 16; o; o >>= 1) v += __shfl_xor_sync(0xffffffffu, v, o);
    if ((tid & 31) == 0) red[tid >> 5] = v;
    __syncthreads();
    if (tid == 0) red[0] = red[0] + red[1] + red[2] + red[3];
    __syncthreads();
    return red[0];
}

__global__ __launch_bounds__(128)
void epilogue_kernel(const float* __restrict__ bufB,
                     const int* __restrict__ nodeids, const int* __restrict__ edgetypes,
                     const float* __restrict__ base, const float* __restrict__ Wfc,
                     const float* __restrict__ bfc,
                     const float* __restrict__ lng, const float* __restrict__ lnb,
                     const float* __restrict__ Wq, const float* __restrict__ Wk,
                     const float* __restrict__ Wv, const float* __restrict__ Wo,
                     const float* __restrict__ reflect, float* __restrict__ out)
{
    __shared__ float spec[3][D_];
    __shared__ float hn[D_], qn[D_];
    __shared__ float Qs[D_], Ks[3][D_], Vs[3][D_];
    __shared__ float ctx[D_], sel[D_];
    __shared__ float tmp[DIN_];
    __shared__ float red[4];
    __shared__ float sca;
    __shared__ float sc[3];

    const int tid = threadIdx.x;

    for (int bb = 0; bb < 4; bb++) {
        const int b = blockIdx.x * 4 + bb;

        // per-g: l2norm + FC
        for (int g = 0; g < 3; g++) {
            float v = (tid < D_) ? bufB[(size_t)g * GSTRIDE + (size_t)b * D_ + tid] : 0.f;
            float ss = bsum128(v * v, red, tid);
            if (tid == 0) sca = 1.f / fmaxf(sqrtf(ss), 1e-12f);
            __syncthreads();
            if (tid < D_) hn[tid] = v * sca;
            __syncthreads();
            if (tid < D_) {
                const float* W = Wfc + (size_t)g * D_ * D_;
                float acc = bfc[g * D_ + tid];
                for (int k = 0; k < D_; k++) acc += hn[k] * W[k * D_ + tid];
                spec[g][tid] = acc;
            }
            __syncthreads();
        }

        const int et = edgetypes[b];

        // LayerNorm on spec[et] -> qn
        float x = (tid < D_) ? spec[et][tid] : 0.f;
        float mu = bsum128(x, red, tid) * 0.01f;
        float dd = (tid < D_) ? (x - mu) : 0.f;
        float var = bsum128(dd * dd, red, tid) * 0.01f;
        if (tid < D_) qn[tid] = dd * rsqrtf(var + 1e-6f) * lng[tid] + lnb[tid];
        __syncthreads();

        // Q (for et), K/V (all heads)
        if (tid < D_) {
            float aq = 0.f;
            for (int k = 0; k < D_; k++) aq += qn[k] * Wq[k * D_ + tid];
            Qs[tid] = aq;
            for (int h = 0; h < 3; h++) {
                float ak = 0.f, av = 0.f;
                for (int k = 0; k < D_; k++) {
                    float s = spec[h][k];
                    ak += s * Wk[k * D_ + tid];
                    av += s * Wv[k * D_ + tid];
                }
                Ks[h][tid] = ak;
                Vs[h][tid] = av;
            }
        }
        __syncthreads();

        // attention scores + softmax (3-way)
        for (int h = 0; h < 3; h++) {
            float p = (tid < D_) ? Qs[tid] * Ks[h][tid] : 0.f;
            float s = bsum128(p, red, tid);
            if (tid == 0) sc[h] = s * 0.1f;  // 1/sqrt(100)
        }
        __syncthreads();
        float m = fmaxf(sc[0], fmaxf(sc[1], sc[2]));
        float e0 = expf(sc[0] - m), e1 = expf(sc[1] - m), e2 = expf(sc[2] - m);
        float inv = 1.f / (e0 + e1 + e2);
        float a0 = e0 * inv, a1 = e1 * inv, a2 = e2 * inv;
        if (tid < D_) ctx[tid] = a0 * Vs[0][tid] + a1 * Vs[1][tid] + a2 * Vs[2][tid];
        __syncthreads();
        if (tid < D_) {
            float acc = spec[et][tid];  // residual
            for (int k = 0; k < D_; k++) acc += ctx[k] * Wo[k * D_ + tid];
            sel[tid] = acc;
        }
        __syncthreads();

        // reflect + base + final l2norm
        const int nid = nodeids[b];
        const float* R = reflect + (size_t)et * D_ * DIN_;
        float lss = 0.f;
        for (int o = tid; o < DIN_; o += 128) {
            float acc = 0.f;
            for (int d = 0; d < D_; d++) acc += sel[d] * R[d * DIN_ + o];
            float r = base[(size_t)nid * DIN_ + o] + acc;
            tmp[o] = r;
            lss += r * r;
        }
        float ss = bsum128(lss, red, tid);
        if (tid == 0) sca = 1.f / fmaxf(sqrtf(ss), 1e-12f);
        __syncthreads();
        for (int o = tid; o < DIN_; o += 128) out[(size_t)b * DIN_ + o] = tmp[o] * sca;
        __syncthreads();
    }
}

#define SMEM_BYTES ((2 * D_ * STP + D_ * D_ + D_) * 4)

extern "C" void kernel_launch(void* const* d_in, const int* in_sizes, int n_in,
                              void* d_out, int out_size) {
    const int*   nodeids   = (const int*)d_in[0];
    const int*   edgetypes = (const int*)d_in[1];
    const int*   n0        = (const int*)d_in[2];
    const int*   n1        = (const int*)d_in[3];
    const int*   n2        = (const int*)d_in[4];
    const int*   n3        = (const int*)d_in[5];
    const float* base      = (const float*)d_in[6];
    const float* emb       = (const float*)d_in[7];
    const float* Wself     = (const float*)d_in[8];
    const float* bself     = (const float*)d_in[9];
    const float* Wneigh    = (const float*)d_in[10];
    const float* bneigh    = (const float*)d_in[11];
    const float* Wfc       = (const float*)d_in[12];
    const float* bfc       = (const float*)d_in[13];
    const float* lng       = (const float*)d_in[14];
    const float* lnb       = (const float*)d_in[15];
    const float* Wq        = (const float*)d_in[16];
    const float* Wk        = (const float*)d_in[17];
    const float* Wv        = (const float*)d_in[18];
    const float* Wo        = (const float*)d_in[19];
    const float* reflect   = (const float*)d_in[20];
    float* out = (float*)d_out;

    float *bufA, *bufB;
    cudaGetSymbolAddress((void**)&bufA, g_bufA);
    cudaGetSymbolAddress((void**)&bufB, g_bufB);

    cudaFuncSetAttribute(pass0_kernel<3>, cudaFuncAttributeMaxDynamicSharedMemorySize, SMEM_BYTES);
    cudaFuncSetAttribute(pass0_kernel<5>, cudaFuncAttributeMaxDynamicSharedMemorySize, SMEM_BYTES);
    cudaFuncSetAttribute(pass0_kernel<7>, cudaFuncAttributeMaxDynamicSharedMemorySize, SMEM_BYTES);
    cudaFuncSetAttribute(pass0_kernel<9>, cudaFuncAttributeMaxDynamicSharedMemorySize, SMEM_BYTES);
    cudaFuncSetAttribute(passN_kernel<3>, cudaFuncAttributeMaxDynamicSharedMemorySize, SMEM_BYTES);
    cudaFuncSetAttribute(passN_kernel<5>, cudaFuncAttributeMaxDynamicSharedMemorySize, SMEM_BYTES);
    cudaFuncSetAttribute(passN_kernel<7>, cudaFuncAttributeMaxDynamicSharedMemorySize, SMEM_BYTES);

    // ---- pass 0 (gathered) -> bufA ----
    pass0_kernel<3><<<dim3(512 / 64, 3),   NTHR, SMEM_BYTES>>>(emb, nodeids, 0,     n0, 1536,
        Wself, Wneigh, bself, bneigh, bufA, 0);
    pass0_kernel<5><<<dim3(1536 / 64, 3),  NTHR, SMEM_BYTES>>>(emb, n0, 1536,       n1, 7680,
        Wself, Wneigh, bself, bneigh, bufA, 512);
    pass0_kernel<7><<<dim3(7680 / 64, 3),  NTHR, SMEM_BYTES>>>(emb, n1, 7680,       n2, 53760,
        Wself, Wneigh, bself, bneigh, bufA, 2048);
    pass0_kernel<9><<<dim3(53760 / 64, 3), NTHR, SMEM_BYTES>>>(emb, n2, 53760,      n3, 483840,
        Wself, Wneigh, bself, bneigh, bufA, 9728);

    // ---- pass 1: bufA -> bufB ----
    passN_kernel<3><<<dim3(512 / 64, 3),  NTHR, SMEM_BYTES>>>(bufA, 0,    512,
        Wself, Wneigh, bself, bneigh, 1, bufB, 0);
    passN_kernel<5><<<dim3(1536 / 64, 3), NTHR, SMEM_BYTES>>>(bufA, 512,  2048,
        Wself, Wneigh, bself, bneigh, 1, bufB, 512);
    passN_kernel<7><<<dim3(7680 / 64, 3), NTHR, SMEM_BYTES>>>(bufA, 2048, 9728,
        Wself, Wneigh, bself, bneigh, 1, bufB, 2048);

    // ---- pass 2: bufB -> bufA ----
    passN_kernel<3><<<dim3(512 / 64, 3),  NTHR, SMEM_BYTES>>>(bufB, 0,   512,
        Wself, Wneigh, bself, bneigh, 2, bufA, 0);
    passN_kernel<5><<<dim3(1536 / 64, 3), NTHR, SMEM_BYTES>>>(bufB, 512, 2048,
        Wself, Wneigh, bself, bneigh, 2, bufA, 512);

    // ---- pass 3: bufA -> bufB ----
    passN_kernel<3><<<dim3(512 / 64, 3), NTHR, SMEM_BYTES>>>(bufA, 0, 512,
        Wself, Wneigh, bself, bneigh, 3, bufB, 0);

    // ---- epilogue ----
    epilogue_kernel<<<B_ / 4, 128>>>(bufB, nodeids, edgetypes, base, Wfc, bfc,
                                     lng, lnb, Wq, Wk, Wv, Wo, reflect, out);
}

// round 3
// speedup vs baseline: 1.5359x; 1.5359x over previous
#include <cuda_runtime.h>
#include <math.h>

#define D_      100
#define DH_     50
#define B_      512
#define G_      3
#define NTAB    100000
#define DIN_    200
#define GSTRIDE 6348800      // 63488 * 100 floats per graph
#define STP     66           // even pitch (8B-aligned float2 LDS), conflicts handled by xor swizzle
#define TILE    64
#define NTHR    160          // GEMM map: 20 col-threads x 8 row-threads

__device__ float g_bufA[G_ * 63488 * D_];
__device__ float g_bufB[G_ * 63488 * D_];

typedef unsigned long long ull;

__device__ __forceinline__ ull pk2(float lo, float hi) {
    ull r; asm("mov.b64 %0, {%1, %2};" : "=l"(r) : "f"(lo), "f"(hi)); return r;
}
__device__ __forceinline__ float2 upk2(ull v) {
    float2 f; asm("mov.b64 {%0, %1}, %2;" : "=f"(f.x), "=f"(f.y) : "l"(v)); return f;
}
#define FMA2(acc, a, b) asm("fma.rn.f32x2 %0, %1, %2, %0;" : "+l"(acc) : "l"(a), "l"(b))

// Tile layout: logical element (k, m) stored at smem[k*STP + (m ^ (2*(k>>4)))].
// Swizzle is even-valued -> float2 pairs (even m, m+1) stay adjacent & 8B-aligned.

// out[m][j] = relu( sum_k src(j)[k][m] * sW[k][j] + sB[j] ); src = X (j<50) else NB.
__device__ __forceinline__ void gemm_relu_store(
    const float* sXT, const float* sNT, const float* sW, const float* sB,
    float* outRow0, int tid)
{
    const int ct = tid % 20, rt = tid / 20;
    const int j0 = ct * 5, mr = rt * 8;
    const float* aT = (j0 < DH_) ? sXT : sNT;
    ull acc[4][5];
#pragma unroll
    for (int c = 0; c < 5; c++) {
        float b = sB[j0 + c];
        ull bb = pk2(b, b);
        acc[0][c] = bb; acc[1][c] = bb; acc[2][c] = bb; acc[3][c] = bb;
    }
#pragma unroll
    for (int kb = 0; kb < 7; kb++) {
        const int sw  = 2 * kb;          // swizzle value for k in [16kb, 16kb+16)
        const int s12 = sw & 6;
        const int mr2 = mr ^ (sw & 8);
        const float* base = aT + mr2;
        const int kmax = (kb == 6) ? 4 : 16;
#pragma unroll 4
        for (int kk = 0; kk < kmax; kk++) {
            const int k = kb * 16 + kk;
            const float* ak = base + k * STP;
            ull x0 = *(const ull*)(ak + (0 ^ s12));   // logical m pair (mr+0, mr+1)
            ull x1 = *(const ull*)(ak + (2 ^ s12));
            ull x2 = *(const ull*)(ak + (4 ^ s12));
            ull x3 = *(const ull*)(ak + (6 ^ s12));
            const float* wk = sW + k * D_ + j0;
#pragma unroll
            for (int c = 0; c < 5; c++) {
                float w = wk[c];
                ull wd = pk2(w, w);
                FMA2(acc[0][c], x0, wd);
                FMA2(acc[1][c], x1, wd);
                FMA2(acc[2][c], x2, wd);
                FMA2(acc[3][c], x3, wd);
            }
        }
    }
#pragma unroll
    for (int r = 0; r < 4; r++) {
        float* o0 = outRow0 + (size_t)(mr + 2 * r) * D_ + j0;
        float* o1 = o0 + D_;
#pragma unroll
        for (int c = 0; c < 5; c++) {
            float2 v = upk2(acc[r][c]);
            o0[c] = fmaxf(v.x, 0.f);
            o1[c] = fmaxf(v.y, 0.f);
        }
    }
}

__device__ __forceinline__ void load_weights(
    const float* Ws, const float* Wn, const float* bs, const float* bn,
    float* sW, float* sB, int tid)
{
    for (int idx = tid; idx < D_ * DH_; idx += NTHR) {
        int i = idx / DH_, j = idx % DH_;
        sW[i * D_ + j]       = Ws[idx];
        sW[i * D_ + DH_ + j] = Wn[idx];
    }
    for (int j = tid; j < DH_; j += NTHR) {
        sB[j]       = bs[j];
        sB[DH_ + j] = bn[j];
    }
}

// store one float4 (k=4q..4q+3, row m) into transposed+swizzled tile
__device__ __forceinline__ void store_t4(float* sT, int m, int q, float4 v) {
    int col = m ^ (2 * (q >> 2));
    int k = q * 4;
    sT[(k + 0) * STP + col] = v.x;
    sT[(k + 1) * STP + col] = v.y;
    sT[(k + 2) * STP + col] = v.z;
    sT[(k + 3) * STP + col] = v.w;
}

// ---------- pass 0 body: gathered from embedding table ----------
template<int S_>
__device__ void pass0_body(const float* __restrict__ emb,
                           const int* __restrict__ xidx, int xstride,
                           const int* __restrict__ nidx, int nstride,
                           const float* __restrict__ Wself, const float* __restrict__ Wneigh,
                           const float* __restrict__ bself, const float* __restrict__ bneigh,
                           float* __restrict__ outbuf, int out_off, int bxl, int g)
{
    extern __shared__ float smem[];
    float* sXT = smem;                 // 100*STP
    float* sNT = smem + D_ * STP;      // 100*STP
    float* sW  = smem + 2 * D_ * STP;  // 100*100
    float* sB  = sW + D_ * D_;         // 104
    int*   sXI = (int*)(sB + 104);     // 64
    int*   sNI = sXI + TILE;           // 64*S_ (max 576)

    const int tid  = threadIdx.x;
    const int row0 = bxl * TILE;

    load_weights(Wself  + (size_t)(g * 4) * D_ * DH_,
                 Wneigh + (size_t)(g * 4) * D_ * DH_,
                 bself  + (size_t)(g * 4) * DH_,
                 bneigh + (size_t)(g * 4) * DH_, sW, sB, tid);

    const int* xg = xidx + (size_t)g * xstride;
    const int* ng = nidx + (size_t)g * nstride;
    if (tid < TILE) sXI[tid] = xg[row0 + tid];
    for (int i = tid; i < TILE * S_; i += NTHR) sNI[i] = ng[(size_t)row0 * S_ + i];
    __syncthreads();

    const float4* e4 = (const float4*)(emb + (size_t)g * NTAB * D_);

    // X gather: one 32-lane group per row, lanes q=0..24 load contiguous float4s
    for (int idx = tid; idx < TILE * 32; idx += NTHR) {
        int m = idx >> 5, q = idx & 31;
        if (q < 25) {
            float4 v = e4[(size_t)sXI[m] * 25 + q];
            store_t4(sXT, m, q, v);
        }
    }
    // neighbor gather + mean
    const float invS = 1.f / (float)S_;
    for (int idx = tid; idx < TILE * 32; idx += NTHR) {
        int m = idx >> 5, q = idx & 31;
        if (q < 25) {
            const int* np = sNI + m * S_;
            float ax = 0.f, ay = 0.f, az = 0.f, aw = 0.f;
#pragma unroll
            for (int s = 0; s < S_; s++) {
                float4 v = e4[(size_t)np[s] * 25 + q];
                ax += v.x; ay += v.y; az += v.z; aw += v.w;
            }
            float4 r; r.x = ax * invS; r.y = ay * invS; r.z = az * invS; r.w = aw * invS;
            store_t4(sNT, m, q, r);
        }
    }
    __syncthreads();

    float* outRow0 = outbuf + (size_t)g * GSTRIDE + (size_t)(out_off + row0) * D_;
    gemm_relu_store(sXT, sNT, sW, sB, outRow0, tid);
}

// ---------- pass 1..3 body: contiguous buffer inputs ----------
template<int S_>
__device__ void passN_body(const float* __restrict__ inbuf, int x_off, int nb_off,
                           const float* __restrict__ Wself, const float* __restrict__ Wneigh,
                           const float* __restrict__ bself, const float* __restrict__ bneigh,
                           int l, float* __restrict__ outbuf, int out_off, int bxl, int g)
{
    extern __shared__ float smem[];
    float* sXT = smem;
    float* sNT = smem + D_ * STP;
    float* sW  = smem + 2 * D_ * STP;
    float* sB  = sW + D_ * D_;

    const int tid  = threadIdx.x;
    const int row0 = bxl * TILE;

    load_weights(Wself  + (size_t)(g * 4 + l) * D_ * DH_,
                 Wneigh + (size_t)(g * 4 + l) * D_ * DH_,
                 bself  + (size_t)(g * 4 + l) * DH_,
                 bneigh + (size_t)(g * 4 + l) * DH_, sW, sB, tid);
    __syncthreads();

    const float* inG = inbuf + (size_t)g * GSTRIDE;

    for (int idx = tid; idx < TILE * 32; idx += NTHR) {
        int m = idx >> 5, q = idx & 31;
        if (q < 25) {
            float4 v = *(const float4*)(inG + (size_t)(x_off + row0 + m) * D_ + q * 4);
            store_t4(sXT, m, q, v);
        }
    }
    const float invS = 1.f / (float)S_;
    for (int idx = tid; idx < TILE * 32; idx += NTHR) {
        int m = idx >> 5, q = idx & 31;
        if (q < 25) {
            const float* p = inG + ((size_t)nb_off + (size_t)(row0 + m) * S_) * D_ + q * 4;
            float ax = 0.f, ay = 0.f, az = 0.f, aw = 0.f;
#pragma unroll
            for (int s = 0; s < S_; s++) {
                float4 v = *(const float4*)(p + (size_t)s * D_);
                ax += v.x; ay += v.y; az += v.z; aw += v.w;
            }
            float4 r; r.x = ax * invS; r.y = ay * invS; r.z = az * invS; r.w = aw * invS;
            store_t4(sNT, m, q, r);
        }
    }
    __syncthreads();

    float* outRow0 = outbuf + (size_t)g * GSTRIDE + (size_t)(out_off + row0) * D_;
    gemm_relu_store(sXT, sNT, sW, sB, outRow0, tid);
}

// ---------- fused launches (independent segments in one grid, biggest first) ----------
__global__ __launch_bounds__(NTHR)
void pass0_fused(const float* __restrict__ emb,
                 const int* __restrict__ nodeids, const int* __restrict__ n0,
                 const int* __restrict__ n1, const int* __restrict__ n2,
                 const int* __restrict__ n3,
                 const float* __restrict__ Ws, const float* __restrict__ Wn,
                 const float* __restrict__ bs, const float* __restrict__ bn,
                 float* __restrict__ outbuf)
{
    const int bx = blockIdx.x, g = blockIdx.y;
    if      (bx < 840) pass0_body<9>(emb, n2, 53760, n3, 483840, Ws, Wn, bs, bn, outbuf, 9728, bx,       g);
    else if (bx < 960) pass0_body<7>(emb, n1, 7680,  n2, 53760,  Ws, Wn, bs, bn, outbuf, 2048, bx - 840, g);
    else if (bx < 984) pass0_body<5>(emb, n0, 1536,  n1, 7680,   Ws, Wn, bs, bn, outbuf, 512,  bx - 960, g);
    else               pass0_body<3>(emb, nodeids, 0, n0, 1536,  Ws, Wn, bs, bn, outbuf, 0,    bx - 984, g);
}

__global__ __launch_bounds__(NTHR)
void pass1_fused(const float* __restrict__ inbuf,
                 const float* __restrict__ Ws, const float* __restrict__ Wn,
                 const float* __restrict__ bs, const float* __restrict__ bn,
                 float* __restrict__ outbuf)
{
    const int bx = blockIdx.x, g = blockIdx.y;
    if      (bx < 120) passN_body<7>(inbuf, 2048, 9728, Ws, Wn, bs, bn, 1, outbuf, 2048, bx,       g);
    else if (bx < 144) passN_body<5>(inbuf, 512,  2048, Ws, Wn, bs, bn, 1, outbuf, 512,  bx - 120, g);
    else               passN_body<3>(inbuf, 0,    512,  Ws, Wn, bs, bn, 1, outbuf, 0,    bx - 144, g);
}

__global__ __launch_bounds__(NTHR)
void pass2_fused(const float* __restrict__ inbuf,
                 const float* __restrict__ Ws, const float* __restrict__ Wn,
                 const float* __restrict__ bs, const float* __restrict__ bn,
                 float* __restrict__ outbuf)
{
    const int bx = blockIdx.x, g = blockIdx.y;
    if (bx < 24) passN_body<5>(inbuf, 512, 2048, Ws, Wn, bs, bn, 2, outbuf, 512, bx,      g);
    else         passN_body<3>(inbuf, 0,   512,  Ws, Wn, bs, bn, 2, outbuf, 0,   bx - 24, g);
}

__global__ __launch_bounds__(NTHR)
void pass3_kernel(const float* __restrict__ inbuf,
                  const float* __restrict__ Ws, const float* __restrict__ Wn,
                  const float* __restrict__ bs, const float* __restrict__ bn,
                  float* __restrict__ outbuf)
{
    passN_body<3>(inbuf, 0, 512, Ws, Wn, bs, bn, 3, outbuf, 0, blockIdx.x, blockIdx.y);
}

// ---------- epilogue: FC + attention + reflect + final l2norm ----------
__device__ __forceinline__ float bsum128(float v, float* red, int tid) {
    __syncthreads();
#pragma unroll
    for (int o = 16; o; o >>= 1) v += __shfl_xor_sync(0xffffffffu, v, o);
    if ((tid & 31) == 0) red[tid >> 5] = v;
    __syncthreads();
    if (tid == 0) red[0] = red[0] + red[1] + red[2] + red[3];
    __syncthreads();
    return red[0];
}

__global__ __launch_bounds__(128)
void epilogue_kernel(const float* __restrict__ bufB,
                     const int* __restrict__ nodeids, const int* __restrict__ edgetypes,
                     const float* __restrict__ base, const float* __restrict__ Wfc,
                     const float* __restrict__ bfc,
                     const float* __restrict__ lng, const float* __restrict__ lnb,
                     const float* __restrict__ Wq, const float* __restrict__ Wk,
                     const float* __restrict__ Wv, const float* __restrict__ Wo,
                     const float* __restrict__ reflect, float* __restrict__ out)
{
    __shared__ float spec[3][D_];
    __shared__ float hn[D_], qn[D_];
    __shared__ float Qs[D_], Ks[3][D_], Vs[3][D_];
    __shared__ float ctx[D_], sel[D_];
    __shared__ float tmp[DIN_];
    __shared__ float red[4];
    __shared__ float sca;
    __shared__ float sc[3];

    const int tid = threadIdx.x;

    for (int bb = 0; bb < 4; bb++) {
        const int b = blockIdx.x * 4 + bb;

        for (int g = 0; g < 3; g++) {
            float v = (tid < D_) ? bufB[(size_t)g * GSTRIDE + (size_t)b * D_ + tid] : 0.f;
            float ss = bsum128(v * v, red, tid);
            if (tid == 0) sca = 1.f / fmaxf(sqrtf(ss), 1e-12f);
            __syncthreads();
            if (tid < D_) hn[tid] = v * sca;
            __syncthreads();
            if (tid < D_) {
                const float* W = Wfc + (size_t)g * D_ * D_;
                float acc = bfc[g * D_ + tid];
                for (int k = 0; k < D_; k++) acc += hn[k] * W[k * D_ + tid];
                spec[g][tid] = acc;
            }
            __syncthreads();
        }

        const int et = edgetypes[b];

        float x = (tid < D_) ? spec[et][tid] : 0.f;
        float mu = bsum128(x, red, tid) * 0.01f;
        float dd = (tid < D_) ? (x - mu) : 0.f;
        float var = bsum128(dd * dd, red, tid) * 0.01f;
        if (tid < D_) qn[tid] = dd * rsqrtf(var + 1e-6f) * lng[tid] + lnb[tid];
        __syncthreads();

        if (tid < D_) {
            float aq = 0.f;
            for (int k = 0; k < D_; k++) aq += qn[k] * Wq[k * D_ + tid];
            Qs[tid] = aq;
            for (int h = 0; h < 3; h++) {
                float ak = 0.f, av = 0.f;
                for (int k = 0; k < D_; k++) {
                    float s = spec[h][k];
                    ak += s * Wk[k * D_ + tid];
                    av += s * Wv[k * D_ + tid];
                }
                Ks[h][tid] = ak;
                Vs[h][tid] = av;
            }
        }
        __syncthreads();

        for (int h = 0; h < 3; h++) {
            float p = (tid < D_) ? Qs[tid] * Ks[h][tid] : 0.f;
            float s = bsum128(p, red, tid);
            if (tid == 0) sc[h] = s * 0.1f;  // 1/sqrt(100)
        }
        __syncthreads();
        float m = fmaxf(sc[0], fmaxf(sc[1], sc[2]));
        float e0 = expf(sc[0] - m), e1 = expf(sc[1] - m), e2 = expf(sc[2] - m);
        float inv = 1.f / (e0 + e1 + e2);
        float a0 = e0 * inv, a1 = e1 * inv, a2 = e2 * inv;
        if (tid < D_) ctx[tid] = a0 * Vs[0][tid] + a1 * Vs[1][tid] + a2 * Vs[2][tid];
        __syncthreads();
        if (tid < D_) {
            float acc = spec[et][tid];  // residual
            for (int k = 0; k < D_; k++) acc += ctx[k] * Wo[k * D_ + tid];
            sel[tid] = acc;
        }
        __syncthreads();

        const int nid = nodeids[b];
        const float* R = reflect + (size_t)et * D_ * DIN_;
        float lss = 0.f;
        for (int o = tid; o < DIN_; o += 128) {
            float acc = 0.f;
            for (int d = 0; d < D_; d++) acc += sel[d] * R[d * DIN_ + o];
            float r = base[(size_t)nid * DIN_ + o] + acc;
            tmp[o] = r;
            lss += r * r;
        }
        float ss = bsum128(lss, red, tid);
        if (tid == 0) sca = 1.f / fmaxf(sqrtf(ss), 1e-12f);
        __syncthreads();
        for (int o = tid; o < DIN_; o += 128) out[(size_t)b * DIN_ + o] = tmp[o] * sca;
        __syncthreads();
    }
}

// floats: 2*100*66 + 100*100 + 104 = 23404 ; ints: 64 + 576 = 640
#define SMEM_BYTES ((2 * D_ * STP + D_ * D_ + 104 + 64 + TILE * 9) * 4)

extern "C" void kernel_launch(void* const* d_in, const int* in_sizes, int n_in,
                              void* d_out, int out_size) {
    const int*   nodeids   = (const int*)d_in[0];
    const int*   edgetypes = (const int*)d_in[1];
    const int*   n0        = (const int*)d_in[2];
    const int*   n1        = (const int*)d_in[3];
    const int*   n2        = (const int*)d_in[4];
    const int*   n3        = (const int*)d_in[5];
    const float* base      = (const float*)d_in[6];
    const float* emb       = (const float*)d_in[7];
    const float* Wself     = (const float*)d_in[8];
    const float* bself     = (const float*)d_in[9];
    const float* Wneigh    = (const float*)d_in[10];
    const float* bneigh    = (const float*)d_in[11];
    const float* Wfc       = (const float*)d_in[12];
    const float* bfc       = (const float*)d_in[13];
    const float* lng       = (const float*)d_in[14];
    const float* lnb       = (const float*)d_in[15];
    const float* Wq        = (const float*)d_in[16];
    const float* Wk        = (const float*)d_in[17];
    const float* Wv        = (const float*)d_in[18];
    const float* Wo        = (const float*)d_in[19];
    const float* reflect   = (const float*)d_in[20];
    float* out = (float*)d_out;

    float *bufA, *bufB;
    cudaGetSymbolAddress((void**)&bufA, g_bufA);
    cudaGetSymbolAddress((void**)&bufB, g_bufB);

    cudaFuncSetAttribute(pass0_fused,  cudaFuncAttributeMaxDynamicSharedMemorySize, SMEM_BYTES);
    cudaFuncSetAttribute(pass1_fused,  cudaFuncAttributeMaxDynamicSharedMemorySize, SMEM_BYTES);
    cudaFuncSetAttribute(pass2_fused,  cudaFuncAttributeMaxDynamicSharedMemorySize, SMEM_BYTES);
    cudaFuncSetAttribute(pass3_kernel, cudaFuncAttributeMaxDynamicSharedMemorySize, SMEM_BYTES);

    pass0_fused<<<dim3(992, 3), NTHR, SMEM_BYTES>>>(emb, nodeids, n0, n1, n2, n3,
                                                    Wself, Wneigh, bself, bneigh, bufA);
    pass1_fused<<<dim3(152, 3), NTHR, SMEM_BYTES>>>(bufA, Wself, Wneigh, bself, bneigh, bufB);
    pass2_fused<<<dim3(32, 3),  NTHR, SMEM_BYTES>>>(bufB, Wself, Wneigh, bself, bneigh, bufA);
    pass3_kernel<<<dim3(8, 3),  NTHR, SMEM_BYTES>>>(bufA, Wself, Wneigh, bself, bneigh, bufB);

    epilogue_kernel<<<B_ / 4, 128>>>(bufB, nodeids, edgetypes, base, Wfc, bfc,
                                     lng, lnb, Wq, Wk, Wv, Wo, reflect, out);
}

// round 4
// speedup vs baseline: 1.6460x; 1.0717x over previous
#include <cuda_runtime.h>
#include <math.h>

#define D_      100
#define DH_     50
#define B_      512
#define G_      3
#define NTAB    100000
#define DIN_    200
#define GSTRIDE 6348800
#define STP     66
#define TILE    64
#define NTHR    160

__device__ float g_bufA[G_ * 63488 * D_];
__device__ float g_bufB[G_ * 63488 * D_];

typedef unsigned long long ull;

__device__ __forceinline__ ull pk2(float lo, float hi) {
    ull r; asm("mov.b64 %0, {%1, %2};" : "=l"(r) : "f"(lo), "f"(hi)); return r;
}
__device__ __forceinline__ float2 upk2(ull v) {
    float2 f; asm("mov.b64 {%0, %1}, %2;" : "=f"(f.x), "=f"(f.y) : "l"(v)); return f;
}
#define FMA2(acc, a, b) asm("fma.rn.f32x2 %0, %1, %2, %0;" : "+l"(acc) : "l"(a), "l"(b))

// ================= pass 0 (gathered, tiled GEMM) =================
__device__ __forceinline__ void gemm_relu_store(
    const float* sXT, const float* sNT, const float* sW, const float* sB,
    float* outRow0, int tid)
{
    const int ct = tid % 20, rt = tid / 20;
    const int j0 = ct * 5, mr = rt * 8;
    const float* aT = (j0 < DH_) ? sXT : sNT;
    ull acc[4][5];
#pragma unroll
    for (int c = 0; c < 5; c++) {
        float b = sB[j0 + c];
        ull bb = pk2(b, b);
        acc[0][c] = bb; acc[1][c] = bb; acc[2][c] = bb; acc[3][c] = bb;
    }
#pragma unroll
    for (int kb = 0; kb < 7; kb++) {
        const int sw  = 2 * kb;
        const int s12 = sw & 6;
        const int mr2 = mr ^ (sw & 8);
        const float* base = aT + mr2;
        const int kmax = (kb == 6) ? 4 : 16;
#pragma unroll 4
        for (int kk = 0; kk < kmax; kk++) {
            const int k = kb * 16 + kk;
            const float* ak = base + k * STP;
            ull x0 = *(const ull*)(ak + (0 ^ s12));
            ull x1 = *(const ull*)(ak + (2 ^ s12));
            ull x2 = *(const ull*)(ak + (4 ^ s12));
            ull x3 = *(const ull*)(ak + (6 ^ s12));
            const float* wk = sW + k * D_ + j0;
#pragma unroll
            for (int c = 0; c < 5; c++) {
                float w = wk[c];
                ull wd = pk2(w, w);
                FMA2(acc[0][c], x0, wd);
                FMA2(acc[1][c], x1, wd);
                FMA2(acc[2][c], x2, wd);
                FMA2(acc[3][c], x3, wd);
            }
        }
    }
#pragma unroll
    for (int r = 0; r < 4; r++) {
        float* o0 = outRow0 + (size_t)(mr + 2 * r) * D_ + j0;
        float* o1 = o0 + D_;
#pragma unroll
        for (int c = 0; c < 5; c++) {
            float2 v = upk2(acc[r][c]);
            o0[c] = fmaxf(v.x, 0.f);
            o1[c] = fmaxf(v.y, 0.f);
        }
    }
}

__device__ __forceinline__ void load_weights(
    const float* Ws, const float* Wn, const float* bs, const float* bn,
    float* sW, float* sB, int tid)
{
    for (int idx = tid; idx < D_ * DH_; idx += NTHR) {
        int i = idx / DH_, j = idx % DH_;
        sW[i * D_ + j]       = Ws[idx];
        sW[i * D_ + DH_ + j] = Wn[idx];
    }
    for (int j = tid; j < DH_; j += NTHR) {
        sB[j]       = bs[j];
        sB[DH_ + j] = bn[j];
    }
}

__device__ __forceinline__ void store_t4(float* sT, int m, int q, float4 v) {
    int col = m ^ (2 * (q >> 2));
    int k = q * 4;
    sT[(k + 0) * STP + col] = v.x;
    sT[(k + 1) * STP + col] = v.y;
    sT[(k + 2) * STP + col] = v.z;
    sT[(k + 3) * STP + col] = v.w;
}

template<int S_>
__device__ void pass0_body(const float* __restrict__ emb,
                           const int* __restrict__ xidx, int xstride,
                           const int* __restrict__ nidx, int nstride,
                           const float* __restrict__ Wself, const float* __restrict__ Wneigh,
                           const float* __restrict__ bself, const float* __restrict__ bneigh,
                           float* __restrict__ outbuf, int out_off, int bxl, int g)
{
    extern __shared__ float smem[];
    float* sXT = smem;
    float* sNT = smem + D_ * STP;
    float* sW  = smem + 2 * D_ * STP;
    float* sB  = sW + D_ * D_;
    int*   sXI = (int*)(sB + 104);
    int*   sNI = sXI + TILE;

    const int tid  = threadIdx.x;
    const int row0 = bxl * TILE;

    load_weights(Wself  + (size_t)(g * 4) * D_ * DH_,
                 Wneigh + (size_t)(g * 4) * D_ * DH_,
                 bself  + (size_t)(g * 4) * DH_,
                 bneigh + (size_t)(g * 4) * DH_, sW, sB, tid);

    const int* xg = xidx + (size_t)g * xstride;
    const int* ng = nidx + (size_t)g * nstride;
    if (tid < TILE) sXI[tid] = xg[row0 + tid];
    for (int i = tid; i < TILE * S_; i += NTHR) sNI[i] = ng[(size_t)row0 * S_ + i];
    __syncthreads();

    const float4* e4 = (const float4*)(emb + (size_t)g * NTAB * D_);

    // full-lane mapping: 1600 work items, no idle lanes
    for (int idx = tid; idx < TILE * 25; idx += NTHR) {
        int m = idx / 25, q = idx - m * 25;
        float4 v = e4[(size_t)sXI[m] * 25 + q];
        store_t4(sXT, m, q, v);
    }
    const float invS = 1.f / (float)S_;
    for (int idx = tid; idx < TILE * 25; idx += NTHR) {
        int m = idx / 25, q = idx - m * 25;
        const int* np = sNI + m * S_;
        float ax = 0.f, ay = 0.f, az = 0.f, aw = 0.f;
#pragma unroll
        for (int s = 0; s < S_; s++) {
            float4 v = e4[(size_t)np[s] * 25 + q];
            ax += v.x; ay += v.y; az += v.z; aw += v.w;
        }
        float4 r; r.x = ax * invS; r.y = ay * invS; r.z = az * invS; r.w = aw * invS;
        store_t4(sNT, m, q, r);
    }
    __syncthreads();

    float* outRow0 = outbuf + (size_t)g * GSTRIDE + (size_t)(out_off + row0) * D_;
    gemm_relu_store(sXT, sNT, sW, sB, outRow0, tid);
}

__global__ __launch_bounds__(NTHR)
void pass0_fused(const float* __restrict__ emb,
                 const int* __restrict__ nodeids, const int* __restrict__ n0,
                 const int* __restrict__ n1, const int* __restrict__ n2,
                 const int* __restrict__ n3,
                 const float* __restrict__ Ws, const float* __restrict__ Wn,
                 const float* __restrict__ bs, const float* __restrict__ bn,
                 float* __restrict__ outbuf)
{
    const int bx = blockIdx.x, g = blockIdx.y;
    if      (bx < 840) pass0_body<9>(emb, n2, 53760, n3, 483840, Ws, Wn, bs, bn, outbuf, 9728, bx,       g);
    else if (bx < 960) pass0_body<7>(emb, n1, 7680,  n2, 53760,  Ws, Wn, bs, bn, outbuf, 2048, bx - 840, g);
    else if (bx < 984) pass0_body<5>(emb, n0, 1536,  n1, 7680,   Ws, Wn, bs, bn, outbuf, 512,  bx - 960, g);
    else               pass0_body<3>(emb, nodeids, 0, n0, 1536,  Ws, Wn, bs, bn, outbuf, 0,    bx - 984, g);
}

// ================= fused tail: passes 1-3 + l2norm + FC, per (b,g) =================
__device__ __forceinline__ float bsum128(float v, float* red, int tid) {
    __syncthreads();
#pragma unroll
    for (int o = 16; o; o >>= 1) v += __shfl_xor_sync(0xffffffffu, v, o);
    if ((tid & 31) == 0) red[tid >> 5] = v;
    __syncthreads();
    if (tid == 0) red[0] = red[0] + red[1] + red[2] + red[3];
    __syncthreads();
    return red[0];
}

__global__ __launch_bounds__(128)
void tail_kernel(const float* __restrict__ bufA,
                 const float* __restrict__ Wself, const float* __restrict__ Wneigh,
                 const float* __restrict__ bself, const float* __restrict__ bneigh,
                 const float* __restrict__ Wfc, const float* __restrict__ bfc,
                 float* __restrict__ spec)
{
    __shared__ __align__(16) float sFT[100 * 20];   // [k][o] self feats: f0|f1(3)|f2(15)|pad
    __shared__ __align__(16) float sMT[100 * 20];   // [k][o] means: mf1|mf2(3)|mf3(15)|pad
    __shared__ __align__(16) float sG1T[100 * 20];  // pass1 out transposed (19 rows)
    __shared__ __align__(16) float mgT[100 * 4];    // pass2 means
    __shared__ __align__(16) float sG2T[100 * 4];   // pass2 out
    __shared__ float m3[100], g3v[100], red[4];
    __shared__ float s_inv;

    const int b = blockIdx.x, g = blockIdx.y, tid = threadIdx.x;
    const float* in = bufA + (size_t)g * GSTRIDE;

    // ---- stage self feats transposed ----
    for (int i = tid; i < 1900; i += 128) {
        int r = i / 100, j = i - r * 100;
        int src = (r == 0) ? b : (r < 4) ? 512 + 3 * b + (r - 1) : 2048 + 15 * b + (r - 4);
        sFT[j * 20 + r] = in[(size_t)src * 100 + j];
    }
    // ---- f3 group means (15 groups of 7) from global ----
    for (int i = tid; i < 1500; i += 128) {
        int r = i / 100, j = i - r * 100;
        const float* p = in + (size_t)(9728 + 105 * b + 7 * r) * 100 + j;
        float a = p[0];
#pragma unroll
        for (int s = 1; s < 7; s++) a += p[s * 100];
        sMT[j * 20 + 4 + r] = a * (1.f / 7.f);
    }
    if (tid < 100) { sFT[tid * 20 + 19] = 0.f; sMT[tid * 20 + 19] = 0.f; }
    __syncthreads();
    // ---- mf1, mf2 from staged rows ----
    for (int i = tid; i < 400; i += 128) {
        int r = i / 100, j = i - r * 100;
        const float* col = sFT + j * 20;
        float a;
        if (r == 0) a = (col[1] + col[2] + col[3]) * (1.f / 3.f);
        else {
            int q = 4 + 5 * (r - 1);
            a = (col[q] + col[q + 1] + col[q + 2] + col[q + 3] + col[q + 4]) * 0.2f;
        }
        sMT[j * 20 + r] = a;
    }
    __syncthreads();

    const bool act  = (tid < 100);
    const bool selfh = (tid < 50);
    const int  jj   = selfh ? tid : tid - 50;

    // ---- pass 1: 19 output rows as 10 packed pairs ----
    {
        const float* W = (selfh ? Wself : Wneigh) + (size_t)(g * 4 + 1) * 5000 + jj;
        const float* src = selfh ? sFT : sMT;
        float bias = act ? (selfh ? bself[(g * 4 + 1) * 50 + jj] : bneigh[(g * 4 + 1) * 50 + jj]) : 0.f;
        ull acc[10];
        ull b2 = pk2(bias, bias);
#pragma unroll
        for (int p = 0; p < 10; p++) acc[p] = b2;
        if (act) {
#pragma unroll 2
            for (int k = 0; k < 100; k++) {
                float w = __ldg(W + k * 50);
                ull w2 = pk2(w, w);
                const ull* x = (const ull*)(src + k * 20);
#pragma unroll
                for (int p = 0; p < 10; p++) FMA2(acc[p], x[p], w2);
            }
            float* o = sG1T + tid * 20;
#pragma unroll
            for (int p = 0; p < 10; p++) {
                float2 v = upk2(acc[p]);
                o[2 * p] = fmaxf(v.x, 0.f);
                if (2 * p + 1 < 19) o[2 * p + 1] = fmaxf(v.y, 0.f);
            }
        }
    }
    __syncthreads();

    // ---- pass 2 means ----
    if (tid < 100) {
        const float* col = sG1T + tid * 20;
        float* mg = mgT + tid * 4;
        mg[0] = (col[1] + col[2] + col[3]) * (1.f / 3.f);
#pragma unroll
        for (int r = 0; r < 3; r++) {
            int q = 4 + 5 * r;
            mg[1 + r] = (col[q] + col[q + 1] + col[q + 2] + col[q + 3] + col[q + 4]) * 0.2f;
        }
    }
    __syncthreads();

    // ---- pass 2: 4 output rows (2 pairs) ----
    {
        const float* W = (selfh ? Wself : Wneigh) + (size_t)(g * 4 + 2) * 5000 + jj;
        const float* src = selfh ? sG1T : mgT;
        const int pitch = selfh ? 20 : 4;
        float bias = act ? (selfh ? bself[(g * 4 + 2) * 50 + jj] : bneigh[(g * 4 + 2) * 50 + jj]) : 0.f;
        ull a0 = pk2(bias, bias), a1 = a0;
        if (act) {
#pragma unroll 2
            for (int k = 0; k < 100; k++) {
                float w = __ldg(W + k * 50);
                ull w2 = pk2(w, w);
                const ull* x = (const ull*)(src + k * pitch);
                FMA2(a0, x[0], w2);
                FMA2(a1, x[1], w2);
            }
            float* o = sG2T + tid * 4;
            float2 v0 = upk2(a0), v1 = upk2(a1);
            o[0] = fmaxf(v0.x, 0.f); o[1] = fmaxf(v0.y, 0.f);
            o[2] = fmaxf(v1.x, 0.f); o[3] = fmaxf(v1.y, 0.f);
        }
    }
    __syncthreads();

    if (tid < 100)
        m3[tid] = (sG2T[tid * 4 + 1] + sG2T[tid * 4 + 2] + sG2T[tid * 4 + 3]) * (1.f / 3.f);
    __syncthreads();

    // ---- pass 3: single row ----
    float g3 = 0.f;
    if (act) {
        const float* W = (selfh ? Wself : Wneigh) + (size_t)(g * 4 + 3) * 5000 + jj;
        float acc = selfh ? bself[(g * 4 + 3) * 50 + jj] : bneigh[(g * 4 + 3) * 50 + jj];
#pragma unroll 4
        for (int k = 0; k < 100; k++) {
            float x = selfh ? sG2T[k * 4] : m3[k];
            acc += x * __ldg(W + k * 50);
        }
        g3 = fmaxf(acc, 0.f);
        g3v[tid] = g3;
    }
    float ss = bsum128(act ? g3 * g3 : 0.f, red, tid);
    if (tid == 0) s_inv = 1.f / fmaxf(sqrtf(ss), 1e-12f);
    __syncthreads();

    // ---- FC -> spec[b][g] ----
    if (tid < 100) {
        const float* Wf = Wfc + (size_t)g * 10000 + tid;
        float acc = 0.f;
#pragma unroll 4
        for (int k = 0; k < 100; k++) acc += g3v[k] * __ldg(Wf + k * 100);
        spec[(size_t)(b * 3 + g) * 100 + tid] = acc * s_inv + bfc[g * 100 + tid];
    }
}

// ================= attention + reflect epilogue, per seed =================
__global__ __launch_bounds__(128)
void attn_kernel(const float* __restrict__ spec,
                 const int* __restrict__ nodeids, const int* __restrict__ edgetypes,
                 const float* __restrict__ base,
                 const float* __restrict__ lng, const float* __restrict__ lnb,
                 const float* __restrict__ Wq, const float* __restrict__ Wk,
                 const float* __restrict__ Wv, const float* __restrict__ Wo,
                 const float* __restrict__ reflect, float* __restrict__ out)
{
    __shared__ float sp[3][D_];
    __shared__ float qn[D_], Qs[D_], Ks[3][D_], Vs[3][D_], ctx[D_], sel[D_];
    __shared__ float tmp[DIN_];
    __shared__ float red[4], sc[3];
    __shared__ float sca;

    const int b = blockIdx.x, tid = threadIdx.x;

    for (int i = tid; i < 300; i += 128) sp[0][i] = spec[(size_t)b * 300 + i];
    __syncthreads();

    const int et = edgetypes[b];

    float x = (tid < D_) ? sp[et][tid] : 0.f;
    float mu = bsum128(x, red, tid) * 0.01f;
    float dd = (tid < D_) ? (x - mu) : 0.f;
    float var = bsum128(dd * dd, red, tid) * 0.01f;
    if (tid < D_) qn[tid] = dd * rsqrtf(var + 1e-6f) * lng[tid] + lnb[tid];
    __syncthreads();

    if (tid < D_) {
        float aq = 0.f;
#pragma unroll 4
        for (int k = 0; k < D_; k++) aq += qn[k] * __ldg(Wq + k * D_ + tid);
        Qs[tid] = aq;
#pragma unroll
        for (int h = 0; h < 3; h++) {
            float ak = 0.f, av = 0.f;
#pragma unroll 4
            for (int k = 0; k < D_; k++) {
                float s = sp[h][k];
                ak += s * __ldg(Wk + k * D_ + tid);
                av += s * __ldg(Wv + k * D_ + tid);
            }
            Ks[h][tid] = ak;
            Vs[h][tid] = av;
        }
    }
    __syncthreads();

    for (int h = 0; h < 3; h++) {
        float p = (tid < D_) ? Qs[tid] * Ks[h][tid] : 0.f;
        float s = bsum128(p, red, tid);
        if (tid == 0) sc[h] = s * 0.1f;
    }
    __syncthreads();
    float m = fmaxf(sc[0], fmaxf(sc[1], sc[2]));
    float e0 = expf(sc[0] - m), e1 = expf(sc[1] - m), e2 = expf(sc[2] - m);
    float inv = 1.f / (e0 + e1 + e2);
    float a0 = e0 * inv, a1 = e1 * inv, a2 = e2 * inv;
    if (tid < D_) ctx[tid] = a0 * Vs[0][tid] + a1 * Vs[1][tid] + a2 * Vs[2][tid];
    __syncthreads();
    if (tid < D_) {
        float acc = sp[et][tid];
#pragma unroll 4
        for (int k = 0; k < D_; k++) acc += ctx[k] * __ldg(Wo + k * D_ + tid);
        sel[tid] = acc;
    }
    __syncthreads();

    const int nid = nodeids[b];
    const float* R = reflect + (size_t)et * D_ * DIN_;
    float lss = 0.f;
    for (int o = tid; o < DIN_; o += 128) {
        float acc = 0.f;
#pragma unroll 4
        for (int d = 0; d < D_; d++) acc += sel[d] * __ldg(R + d * DIN_ + o);
        float r = base[(size_t)nid * DIN_ + o] + acc;
        tmp[o] = r;
        lss += r * r;
    }
    float ss = bsum128(lss, red, tid);
    if (tid == 0) sca = 1.f / fmaxf(sqrtf(ss), 1e-12f);
    __syncthreads();
    for (int o = tid; o < DIN_; o += 128) out[(size_t)b * DIN_ + o] = tmp[o] * sca;
}

#define SMEM_BYTES ((2 * D_ * STP + D_ * D_ + 104 + 64 + TILE * 9) * 4)

extern "C" void kernel_launch(void* const* d_in, const int* in_sizes, int n_in,
                              void* d_out, int out_size) {
    const int*   nodeids   = (const int*)d_in[0];
    const int*   edgetypes = (const int*)d_in[1];
    const int*   n0        = (const int*)d_in[2];
    const int*   n1        = (const int*)d_in[3];
    const int*   n2        = (const int*)d_in[4];
    const int*   n3        = (const int*)d_in[5];
    const float* base      = (const float*)d_in[6];
    const float* emb       = (const float*)d_in[7];
    const float* Wself     = (const float*)d_in[8];
    const float* bself     = (const float*)d_in[9];
    const float* Wneigh    = (const float*)d_in[10];
    const float* bneigh    = (const float*)d_in[11];
    const float* Wfc       = (const float*)d_in[12];
    const float* bfc       = (const float*)d_in[13];
    const float* lng       = (const float*)d_in[14];
    const float* lnb       = (const float*)d_in[15];
    const float* Wq        = (const float*)d_in[16];
    const float* Wk        = (const float*)d_in[17];
    const float* Wv        = (const float*)d_in[18];
    const float* Wo        = (const float*)d_in[19];
    const float* reflect   = (const float*)d_in[20];
    float* out = (float*)d_out;

    float *bufA, *bufB;
    cudaGetSymbolAddress((void**)&bufA, g_bufA);
    cudaGetSymbolAddress((void**)&bufB, g_bufB);

    cudaFuncSetAttribute(pass0_fused, cudaFuncAttributeMaxDynamicSharedMemorySize, SMEM_BYTES);

    pass0_fused<<<dim3(992, 3), NTHR, SMEM_BYTES>>>(emb, nodeids, n0, n1, n2, n3,
                                                    Wself, Wneigh, bself, bneigh, bufA);
    tail_kernel<<<dim3(B_, 3), 128>>>(bufA, Wself, Wneigh, bself, bneigh, Wfc, bfc, bufB);
    attn_kernel<<<B_, 128>>>(bufB, nodeids, edgetypes, base, lng, lnb,
                             Wq, Wk, Wv, Wo, reflect, out);
}

// round 5
// speedup vs baseline: 1.6954x; 1.0300x over previous
#include <cuda_runtime.h>
#include <math.h>

#define D_      100
#define DH_     50
#define B_      512
#define G_      3
#define NTAB    100000
#define DIN_    200
#define GSTRIDE 6348800
#define STP     66
#define TILE    64
#define NTHR    256

__device__ float g_bufA[G_ * 63488 * D_];

typedef unsigned long long ull;

__device__ __forceinline__ ull pk2(float lo, float hi) {
    ull r; asm("mov.b64 %0, {%1, %2};" : "=l"(r) : "f"(lo), "f"(hi)); return r;
}
__device__ __forceinline__ float2 upk2(ull v) {
    float2 f; asm("mov.b64 {%0, %1}, %2;" : "=f"(f.x), "=f"(f.y) : "l"(v)); return f;
}
#define FMA2(acc, a, b) asm("fma.rn.f32x2 %0, %1, %2, %0;" : "+l"(acc) : "l"(a), "l"(b))

// ================= pass 0 (gathered, tiled GEMM) =================
// 200 GEMM threads: ct=tid%50 -> cols j0=2ct,j0+1 ; rt=tid/50 -> rows rt*16..rt*16+15
__device__ __forceinline__ void gemm_relu_store(
    const float* sXT, const float* sNT, const float* sW, const float* sB,
    float* outRow0, int tid)
{
    if (tid >= 200) return;
    const int ct = tid % 50, rt = tid / 50;
    const int j0 = ct * 2, mr = rt * 16;
    const float* aT = (j0 < DH_) ? sXT : sNT;
    ull acc[8][2];
    {
        float b0 = sB[j0], b1 = sB[j0 + 1];
        ull bb0 = pk2(b0, b0), bb1 = pk2(b1, b1);
#pragma unroll
        for (int p = 0; p < 8; p++) { acc[p][0] = bb0; acc[p][1] = bb1; }
    }
#pragma unroll
    for (int kb = 0; kb < 7; kb++) {
        const int sw = 2 * kb;                 // swizzle for k in [16kb,16kb+16)
        const float* base = aT + mr;
        const int kmax = (kb == 6) ? 4 : 16;
#pragma unroll 4
        for (int kk = 0; kk < kmax; kk++) {
            const int k = kb * 16 + kk;
            const float* ak = base + k * STP;
            float2 wv = *(const float2*)(sW + k * D_ + j0);
            ull wd0 = pk2(wv.x, wv.x), wd1 = pk2(wv.y, wv.y);
#pragma unroll
            for (int p = 0; p < 8; p++) {
                ull x = *(const ull*)(ak + ((2 * p) ^ sw));   // rows mr+2p, mr+2p+1
                FMA2(acc[p][0], x, wd0);
                FMA2(acc[p][1], x, wd1);
            }
        }
    }
#pragma unroll
    for (int p = 0; p < 8; p++) {
        float2 v0 = upk2(acc[p][0]);   // (row m0, row m1) for col j0
        float2 v1 = upk2(acc[p][1]);   // for col j0+1
        float* o0 = outRow0 + (size_t)(mr + 2 * p) * D_ + j0;
        float* o1 = o0 + D_;
        float2 r0; r0.x = fmaxf(v0.x, 0.f); r0.y = fmaxf(v1.x, 0.f);
        float2 r1; r1.x = fmaxf(v0.y, 0.f); r1.y = fmaxf(v1.y, 0.f);
        *(float2*)o0 = r0;
        *(float2*)o1 = r1;
    }
}

__device__ __forceinline__ void load_weights(
    const float* Ws, const float* Wn, const float* bs, const float* bn,
    float* sW, float* sB, int tid)
{
    for (int idx = tid; idx < D_ * DH_; idx += NTHR) {
        int i = idx / DH_, j = idx % DH_;
        sW[i * D_ + j]       = Ws[idx];
        sW[i * D_ + DH_ + j] = Wn[idx];
    }
    if (tid < DH_) {
        sB[tid]       = bs[tid];
        sB[DH_ + tid] = bn[tid];
    }
}

__device__ __forceinline__ void store_t4(float* sT, int m, int q, float4 v) {
    int col = m ^ (2 * (q >> 2));
    int k = q * 4;
    sT[(k + 0) * STP + col] = v.x;
    sT[(k + 1) * STP + col] = v.y;
    sT[(k + 2) * STP + col] = v.z;
    sT[(k + 3) * STP + col] = v.w;
}

template<int S_>
__device__ void pass0_body(const float* __restrict__ emb,
                           const int* __restrict__ xidx, int xstride,
                           const int* __restrict__ nidx, int nstride,
                           const float* __restrict__ Wself, const float* __restrict__ Wneigh,
                           const float* __restrict__ bself, const float* __restrict__ bneigh,
                           float* __restrict__ outbuf, int out_off, int bxl, int g)
{
    extern __shared__ float smem[];
    float* sXT = smem;
    float* sNT = smem + D_ * STP;
    float* sW  = smem + 2 * D_ * STP;
    float* sB  = sW + D_ * D_;
    int*   sXI = (int*)(sB + 104);
    int*   sNI = sXI + TILE;

    const int tid  = threadIdx.x;
    const int row0 = bxl * TILE;

    load_weights(Wself  + (size_t)(g * 4) * D_ * DH_,
                 Wneigh + (size_t)(g * 4) * D_ * DH_,
                 bself  + (size_t)(g * 4) * DH_,
                 bneigh + (size_t)(g * 4) * DH_, sW, sB, tid);

    const int* xg = xidx + (size_t)g * xstride;
    const int* ng = nidx + (size_t)g * nstride;
    if (tid < TILE) sXI[tid] = xg[row0 + tid];
    for (int i = tid; i < TILE * S_; i += NTHR) sNI[i] = ng[(size_t)row0 * S_ + i];
    __syncthreads();

    const float4* e4 = (const float4*)(emb + (size_t)g * NTAB * D_);

    for (int idx = tid; idx < TILE * 25; idx += NTHR) {
        int m = idx / 25, q = idx - m * 25;
        float4 v = e4[(size_t)sXI[m] * 25 + q];
        store_t4(sXT, m, q, v);
    }
    const float invS = 1.f / (float)S_;
    for (int idx = tid; idx < TILE * 25; idx += NTHR) {
        int m = idx / 25, q = idx - m * 25;
        const int* np = sNI + m * S_;
        float ax = 0.f, ay = 0.f, az = 0.f, aw = 0.f;
#pragma unroll
        for (int s = 0; s < S_; s++) {
            float4 v = e4[(size_t)np[s] * 25 + q];
            ax += v.x; ay += v.y; az += v.z; aw += v.w;
        }
        float4 r; r.x = ax * invS; r.y = ay * invS; r.z = az * invS; r.w = aw * invS;
        store_t4(sNT, m, q, r);
    }
    __syncthreads();

    float* outRow0 = outbuf + (size_t)g * GSTRIDE + (size_t)(out_off + row0) * D_;
    gemm_relu_store(sXT, sNT, sW, sB, outRow0, tid);
}

__global__ __launch_bounds__(NTHR, 2)
void pass0_fused(const float* __restrict__ emb,
                 const int* __restrict__ nodeids, const int* __restrict__ n0,
                 const int* __restrict__ n1, const int* __restrict__ n2,
                 const int* __restrict__ n3,
                 const float* __restrict__ Ws, const float* __restrict__ Wn,
                 const float* __restrict__ bs, const float* __restrict__ bn,
                 float* __restrict__ outbuf)
{
    const int bx = blockIdx.x, g = blockIdx.y;
    if      (bx < 840) pass0_body<9>(emb, n2, 53760, n3, 483840, Ws, Wn, bs, bn, outbuf, 9728, bx,       g);
    else if (bx < 960) pass0_body<7>(emb, n1, 7680,  n2, 53760,  Ws, Wn, bs, bn, outbuf, 2048, bx - 840, g);
    else if (bx < 984) pass0_body<5>(emb, n0, 1536,  n1, 7680,   Ws, Wn, bs, bn, outbuf, 512,  bx - 960, g);
    else               pass0_body<3>(emb, nodeids, 0, n0, 1536,  Ws, Wn, bs, bn, outbuf, 0,    bx - 984, g);
}

// ================= merged tail: passes 1-3 + FC (3 graphs parallel) + attention =================
// 384 threads = 3 groups of 128 (one per graph g). All __syncthreads reached by all threads.

// smem layout (floats)
#define TGSZ   7008     // per-g region
#define T_FT   0
#define T_MT   2000
#define T_G1   4000
#define T_MG   6000
#define T_G2   6400
#define T_M3   6800
#define T_G3   6904
#define T_CM   (3 * TGSZ)           // common region base = 21024
#define C_SPEC 0
#define C_QN   304
#define C_QS   408
#define C_KS   512
#define C_VS   816
#define C_CTX  1120
#define C_SEL  1224
#define C_TMP  1328
#define C_RED  1536
#define C_RES  1552
#define C_SC   1560
#define TAIL_SMEM ((T_CM + 2048) * 4)

// full-block sum over all 384 threads
__device__ __forceinline__ float bsum384(float v, float* red, int tid) {
    __syncthreads();
#pragma unroll
    for (int o = 16; o; o >>= 1) v += __shfl_xor_sync(0xffffffffu, v, o);
    if ((tid & 31) == 0) red[tid >> 5] = v;
    __syncthreads();
    if (tid == 0) {
        float s = 0.f;
#pragma unroll
        for (int w = 0; w < 12; w++) s += red[w];
        red[0] = s;
    }
    __syncthreads();
    return red[0];
}

__global__ __launch_bounds__(384)
void tail_attn_kernel(const float* __restrict__ bufA,
                      const float* __restrict__ Wself, const float* __restrict__ Wneigh,
                      const float* __restrict__ bself, const float* __restrict__ bneigh,
                      const float* __restrict__ Wfc, const float* __restrict__ bfc,
                      const int* __restrict__ nodeids, const int* __restrict__ edgetypes,
                      const float* __restrict__ base,
                      const float* __restrict__ lng, const float* __restrict__ lnb,
                      const float* __restrict__ Wq, const float* __restrict__ Wk,
                      const float* __restrict__ Wv, const float* __restrict__ Wo,
                      const float* __restrict__ reflect, float* __restrict__ out)
{
    extern __shared__ float sm[];
    const int b   = blockIdx.x;
    const int tid = threadIdx.x;
    const int g   = tid >> 7;          // 0..2
    const int gl  = tid & 127;         // lane within group

    float* gm   = sm + g * TGSZ;
    float* sFT  = gm + T_FT;    // [k][20] self feats f0|f1(3)|f2(15)|pad
    float* sMT  = gm + T_MT;    // [k][20] means
    float* sG1  = gm + T_G1;    // [k][20] pass1 out (19 rows)
    float* sMG  = gm + T_MG;    // [k][4]
    float* sG2  = gm + T_G2;    // [k][4]
    float* sM3  = gm + T_M3;    // [100]
    float* sG3  = gm + T_G3;    // [100]
    float* cm   = sm + T_CM;
    float* spec = cm + C_SPEC;  // [3][100]
    float* red  = cm + C_RED;   // [12+]
    float* res  = cm + C_RES;   // [3] per-g scalars
    float* sc   = cm + C_SC;    // [3]

    const float* in = bufA + (size_t)g * GSTRIDE;

    // ---- stage self feats transposed ----
    for (int i = gl; i < 1900; i += 128) {
        int r = i / 100, j = i - r * 100;
        int src = (r == 0) ? b : (r < 4) ? 512 + 3 * b + (r - 1) : 2048 + 15 * b + (r - 4);
        sFT[j * 20 + r] = in[(size_t)src * 100 + j];
    }
    // ---- f3 group means (15 groups of 7) ----
    for (int i = gl; i < 1500; i += 128) {
        int r = i / 100, j = i - r * 100;
        const float* p = in + (size_t)(9728 + 105 * b + 7 * r) * 100 + j;
        float a = p[0];
#pragma unroll
        for (int s = 1; s < 7; s++) a += p[s * 100];
        sMT[j * 20 + 4 + r] = a * (1.f / 7.f);
    }
    if (gl < 100) { sFT[gl * 20 + 19] = 0.f; sMT[gl * 20 + 19] = 0.f; }
    __syncthreads();
    // ---- mf1, mf2 ----
    for (int i = gl; i < 400; i += 128) {
        int r = i / 100, j = i - r * 100;
        const float* col = sFT + j * 20;
        float a;
        if (r == 0) a = (col[1] + col[2] + col[3]) * (1.f / 3.f);
        else {
            int q = 4 + 5 * (r - 1);
            a = (col[q] + col[q + 1] + col[q + 2] + col[q + 3] + col[q + 4]) * 0.2f;
        }
        sMT[j * 20 + r] = a;
    }
    __syncthreads();

    const bool act   = (gl < 100);
    const bool selfh = (gl < 50);
    const int  jj    = selfh ? gl : gl - 50;

    // ---- pass 1: 19 rows as 10 packed pairs ----
    {
        const float* W = (selfh ? Wself : Wneigh) + (size_t)(g * 4 + 1) * 5000 + jj;
        const float* src = selfh ? sFT : sMT;
        float bias = act ? (selfh ? bself[(g * 4 + 1) * 50 + jj] : bneigh[(g * 4 + 1) * 50 + jj]) : 0.f;
        ull acc[10];
        ull b2 = pk2(bias, bias);
#pragma unroll
        for (int p = 0; p < 10; p++) acc[p] = b2;
        if (act) {
#pragma unroll 2
            for (int k = 0; k < 100; k++) {
                float w = __ldg(W + k * 50);
                ull w2 = pk2(w, w);
                const ull* x = (const ull*)(src + k * 20);
#pragma unroll
                for (int p = 0; p < 10; p++) FMA2(acc[p], x[p], w2);
            }
            float* o = sG1 + gl * 20;
#pragma unroll
            for (int p = 0; p < 10; p++) {
                float2 v = upk2(acc[p]);
                o[2 * p] = fmaxf(v.x, 0.f);
                if (2 * p + 1 < 19) o[2 * p + 1] = fmaxf(v.y, 0.f);
            }
        }
    }
    __syncthreads();

    // ---- pass 2 means ----
    if (gl < 100) {
        const float* col = sG1 + gl * 20;
        float* mg = sMG + gl * 4;
        mg[0] = (col[1] + col[2] + col[3]) * (1.f / 3.f);
#pragma unroll
        for (int r = 0; r < 3; r++) {
            int q = 4 + 5 * r;
            mg[1 + r] = (col[q] + col[q + 1] + col[q + 2] + col[q + 3] + col[q + 4]) * 0.2f;
        }
    }
    __syncthreads();

    // ---- pass 2: 4 rows (2 pairs) ----
    {
        const float* W = (selfh ? Wself : Wneigh) + (size_t)(g * 4 + 2) * 5000 + jj;
        const float* src = selfh ? sG1 : sMG;
        const int pitch = selfh ? 20 : 4;
        float bias = act ? (selfh ? bself[(g * 4 + 2) * 50 + jj] : bneigh[(g * 4 + 2) * 50 + jj]) : 0.f;
        ull a0 = pk2(bias, bias), a1 = a0;
        if (act) {
#pragma unroll 2
            for (int k = 0; k < 100; k++) {
                float w = __ldg(W + k * 50);
                ull w2 = pk2(w, w);
                const ull* x = (const ull*)(src + k * pitch);
                FMA2(a0, x[0], w2);
                FMA2(a1, x[1], w2);
            }
            float* o = sG2 + gl * 4;
            float2 v0 = upk2(a0), v1 = upk2(a1);
            o[0] = fmaxf(v0.x, 0.f); o[1] = fmaxf(v0.y, 0.f);
            o[2] = fmaxf(v1.x, 0.f); o[3] = fmaxf(v1.y, 0.f);
        }
    }
    __syncthreads();

    if (gl < 100)
        sM3[gl] = (sG2[gl * 4 + 1] + sG2[gl * 4 + 2] + sG2[gl * 4 + 3]) * (1.f / 3.f);
    __syncthreads();

    // ---- pass 3: single row + per-group l2norm ----
    float g3 = 0.f;
    if (act) {
        const float* W = (selfh ? Wself : Wneigh) + (size_t)(g * 4 + 3) * 5000 + jj;
        float acc = selfh ? bself[(g * 4 + 3) * 50 + jj] : bneigh[(g * 4 + 3) * 50 + jj];
#pragma unroll 4
        for (int k = 0; k < 100; k++) {
            float x = selfh ? sG2[k * 4] : sM3[k];
            acc += x * __ldg(W + k * 50);
        }
        g3 = fmaxf(acc, 0.f);
        sG3[gl] = g3;
    }
    // per-group sum of g3^2
    {
        float v = act ? g3 * g3 : 0.f;
#pragma unroll
        for (int o = 16; o; o >>= 1) v += __shfl_xor_sync(0xffffffffu, v, o);
        if ((tid & 31) == 0) red[tid >> 5] = v;
        __syncthreads();
        if (gl == 0) {
            float s = red[4 * g] + red[4 * g + 1] + red[4 * g + 2] + red[4 * g + 3];
            res[g] = 1.f / fmaxf(sqrtf(s), 1e-12f);
        }
        __syncthreads();
    }

    // ---- FC -> spec[g] ----
    if (gl < 100) {
        const float* Wf = Wfc + (size_t)g * 10000 + gl;
        float acc = 0.f;
#pragma unroll 4
        for (int k = 0; k < 100; k++) acc += sG3[k] * __ldg(Wf + k * 100);
        spec[g * 100 + gl] = acc * res[g] + bfc[g * 100 + gl];
    }
    __syncthreads();

    // ================= attention + reflect (whole block) =================
    float* qn  = cm + C_QN;
    float* Qs  = cm + C_QS;
    float* Ks  = cm + C_KS;
    float* Vs  = cm + C_VS;
    float* ctx = cm + C_CTX;
    float* sel = cm + C_SEL;
    float* tmp = cm + C_TMP;

    const int et = edgetypes[b];

    // LayerNorm on spec[et]
    float x = (tid < 100) ? spec[et * 100 + tid] : 0.f;
    float mu = bsum384(x, red, tid) * 0.01f;
    float dd = (tid < 100) ? (x - mu) : 0.f;
    float var = bsum384(dd * dd, red, tid) * 0.01f;
    if (tid < 100) qn[tid] = dd * rsqrtf(var + 1e-6f) * lng[tid] + lnb[tid];
    __syncthreads();

    // Q (et only) ; K,V for all heads in parallel (tid<300)
    if (tid < 100) {
        float aq = 0.f;
#pragma unroll 4
        for (int k = 0; k < 100; k++) aq += qn[k] * __ldg(Wq + k * 100 + tid);
        Qs[tid] = aq;
    }
    if (tid < 300) {
        int h = tid / 100, j = tid - h * 100;
        const float* sp = spec + h * 100;
        float ak = 0.f, av = 0.f;
#pragma unroll 4
        for (int k = 0; k < 100; k++) {
            float s = sp[k];
            ak += s * __ldg(Wk + k * 100 + j);
            av += s * __ldg(Wv + k * 100 + j);
        }
        Ks[h * 100 + j] = ak;
        Vs[h * 100 + j] = av;
    }
    __syncthreads();

    for (int h = 0; h < 3; h++) {
        float p = (tid < 100) ? Qs[tid] * Ks[h * 100 + tid] : 0.f;
        float s = bsum384(p, red, tid);
        if (tid == 0) sc[h] = s * 0.1f;     // 1/sqrt(100)
    }
    __syncthreads();
    {
        float m = fmaxf(sc[0], fmaxf(sc[1], sc[2]));
        float e0 = expf(sc[0] - m), e1 = expf(sc[1] - m), e2 = expf(sc[2] - m);
        float inv = 1.f / (e0 + e1 + e2);
        float a0 = e0 * inv, a1 = e1 * inv, a2 = e2 * inv;
        if (tid < 100)
            ctx[tid] = a0 * Vs[tid] + a1 * Vs[100 + tid] + a2 * Vs[200 + tid];
    }
    __syncthreads();
    if (tid < 100) {
        float acc = spec[et * 100 + tid];   // residual
#pragma unroll 4
        for (int k = 0; k < 100; k++) acc += ctx[k] * __ldg(Wo + k * 100 + tid);
        sel[tid] = acc;
    }
    __syncthreads();

    // reflect + base + final l2norm (200 outputs, tid<200)
    const int nid = nodeids[b];
    const float* R = reflect + (size_t)et * 100 * DIN_;
    float lss = 0.f;
    if (tid < DIN_) {
        float acc = 0.f;
#pragma unroll 4
        for (int d = 0; d < 100; d++) acc += sel[d] * __ldg(R + d * DIN_ + tid);
        float r = base[(size_t)nid * DIN_ + tid] + acc;
        tmp[tid] = r;
        lss = r * r;
    }
    float ss = bsum384(lss, red, tid);
    float sca = 1.f / fmaxf(sqrtf(ss), 1e-12f);
    if (tid < DIN_) out[(size_t)b * DIN_ + tid] = tmp[tid] * sca;
}

#define SMEM_BYTES ((2 * D_ * STP + D_ * D_ + 104 + 64 + TILE * 9) * 4)

extern "C" void kernel_launch(void* const* d_in, const int* in_sizes, int n_in,
                              void* d_out, int out_size) {
    const int*   nodeids   = (const int*)d_in[0];
    const int*   edgetypes = (const int*)d_in[1];
    const int*   n0        = (const int*)d_in[2];
    const int*   n1        = (const int*)d_in[3];
    const int*   n2        = (const int*)d_in[4];
    const int*   n3        = (const int*)d_in[5];
    const float* base      = (const float*)d_in[6];
    const float* emb       = (const float*)d_in[7];
    const float* Wself     = (const float*)d_in[8];
    const float* bself     = (const float*)d_in[9];
    const float* Wneigh    = (const float*)d_in[10];
    const float* bneigh    = (const float*)d_in[11];
    const float* Wfc       = (const float*)d_in[12];
    const float* bfc       = (const float*)d_in[13];
    const float* lng       = (const float*)d_in[14];
    const float* lnb       = (const float*)d_in[15];
    const float* Wq        = (const float*)d_in[16];
    const float* Wk        = (const float*)d_in[17];
    const float* Wv        = (const float*)d_in[18];
    const float* Wo        = (const float*)d_in[19];
    const float* reflect   = (const float*)d_in[20];
    float* out = (float*)d_out;

    float *bufA;
    cudaGetSymbolAddress((void**)&bufA, g_bufA);

    cudaFuncSetAttribute(pass0_fused, cudaFuncAttributeMaxDynamicSharedMemorySize, SMEM_BYTES);
    cudaFuncSetAttribute(tail_attn_kernel, cudaFuncAttributeMaxDynamicSharedMemorySize, TAIL_SMEM);

    pass0_fused<<<dim3(992, 3), NTHR, SMEM_BYTES>>>(emb, nodeids, n0, n1, n2, n3,
                                                    Wself, Wneigh, bself, bneigh, bufA);
    tail_attn_kernel<<<B_, 384, TAIL_SMEM>>>(bufA, Wself, Wneigh, bself, bneigh, Wfc, bfc,
                                             nodeids, edgetypes, base, lng, lnb,
                                             Wq, Wk, Wv, Wo, reflect, out);
}

// round 6
// speedup vs baseline: 1.8241x; 1.0760x over previous
#include <cuda_runtime.h>
#include <math.h>

#define D_      100
#define DH_     50
#define B_      512
#define G_      3
#define NTAB    100000
#define DIN_    200
#define GSTRIDE 6348800
#define STP     66
#define TILE    64
#define NTHR    256

__device__ float g_bufA[G_ * 63488 * D_];

typedef unsigned long long ull;

__device__ __forceinline__ ull pk2(float lo, float hi) {
    ull r; asm("mov.b64 %0, {%1, %2};" : "=l"(r) : "f"(lo), "f"(hi)); return r;
}
__device__ __forceinline__ float2 upk2(ull v) {
    float2 f; asm("mov.b64 {%0, %1}, %2;" : "=f"(f.x), "=f"(f.y) : "l"(v)); return f;
}
#define FMA2(acc, a, b) asm("fma.rn.f32x2 %0, %1, %2, %0;" : "+l"(acc) : "l"(a), "l"(b))

// ================= pass 0 (gathered, tiled GEMM; W direct from L1) =================
// 200 GEMM threads: ct=tid%50 -> cols j0=2ct,j0+1 ; rt=tid/50 -> rows rt*16..+15
__device__ __forceinline__ void gemm_relu_store(
    const float* sXT, const float* sNT,
    const float* Ws, const float* Wn, const float* bs, const float* bn,
    float* outRow0, int tid)
{
    if (tid >= 200) return;
    const int ct = tid % 50, rt = tid / 50;
    const int j0 = ct * 2, mr = rt * 16;
    const bool selfh = (j0 < DH_);
    const int jj = selfh ? j0 : j0 - DH_;
    const float* aT = selfh ? sXT : sNT;
    const float* Wp = (selfh ? Ws : Wn) + jj;           // row k at Wp + k*50
    const float* bp = selfh ? bs : bn;

    ull acc[8][2];
    {
        float b0 = bp[jj], b1 = bp[jj + 1];
        ull bb0 = pk2(b0, b0), bb1 = pk2(b1, b1);
#pragma unroll
        for (int p = 0; p < 8; p++) { acc[p][0] = bb0; acc[p][1] = bb1; }
    }
#pragma unroll
    for (int kb = 0; kb < 7; kb++) {
        const int sw = 2 * kb;                            // compile-time
        const int kmax = (kb == 6) ? 4 : 16;
#pragma unroll
        for (int kk = 0; kk < kmax; kk += 8) {
            const int nn = (kmax - kk < 8) ? (kmax - kk) : 8;
            float2 wv[8];
#pragma unroll
            for (int i = 0; i < nn; i++)
                wv[i] = __ldg((const float2*)(Wp + (kb * 16 + kk + i) * DH_));
#pragma unroll
            for (int i = 0; i < nn; i++) {
                const float* ak = aT + (kb * 16 + kk + i) * STP + mr;
                ull wd0 = pk2(wv[i].x, wv[i].x), wd1 = pk2(wv[i].y, wv[i].y);
#pragma unroll
                for (int p = 0; p < 8; p++) {
                    ull x = *(const ull*)(ak + ((2 * p) ^ sw));
                    FMA2(acc[p][0], x, wd0);
                    FMA2(acc[p][1], x, wd1);
                }
            }
        }
    }
#pragma unroll
    for (int p = 0; p < 8; p++) {
        float2 v0 = upk2(acc[p][0]);
        float2 v1 = upk2(acc[p][1]);
        float* o0 = outRow0 + (size_t)(mr + 2 * p) * D_ + j0;
        float* o1 = o0 + D_;
        float2 r0; r0.x = fmaxf(v0.x, 0.f); r0.y = fmaxf(v1.x, 0.f);
        float2 r1; r1.x = fmaxf(v0.y, 0.f); r1.y = fmaxf(v1.y, 0.f);
        *(float2*)o0 = r0;
        *(float2*)o1 = r1;
    }
}

__device__ __forceinline__ void store_t4(float* sT, int m, int q, float4 v) {
    int col = m ^ (2 * (q >> 2));
    int k = q * 4;
    sT[(k + 0) * STP + col] = v.x;
    sT[(k + 1) * STP + col] = v.y;
    sT[(k + 2) * STP + col] = v.z;
    sT[(k + 3) * STP + col] = v.w;
}

template<int S_>
__device__ void pass0_body(const float* __restrict__ emb,
                           const int* __restrict__ xidx, int xstride,
                           const int* __restrict__ nidx, int nstride,
                           const float* __restrict__ Wself, const float* __restrict__ Wneigh,
                           const float* __restrict__ bself, const float* __restrict__ bneigh,
                           float* __restrict__ outbuf, int out_off, int bxl, int g)
{
    extern __shared__ float smem[];
    float* sXT = smem;
    float* sNT = smem + D_ * STP;
    int*   sXI = (int*)(smem + 2 * D_ * STP + 16);
    int*   sNI = sXI + TILE;

    const int tid  = threadIdx.x;
    const int row0 = bxl * TILE;

    const int* xg = xidx + (size_t)g * xstride;
    const int* ng = nidx + (size_t)g * nstride;
    if (tid < TILE) sXI[tid] = xg[row0 + tid];
    for (int i = tid; i < TILE * S_; i += NTHR) sNI[i] = ng[(size_t)row0 * S_ + i];
    __syncthreads();

    const float4* e4 = (const float4*)(emb + (size_t)g * NTAB * D_);

    for (int idx = tid; idx < TILE * 25; idx += NTHR) {
        int m = idx / 25, q = idx - m * 25;
        float4 v = e4[(size_t)sXI[m] * 25 + q];
        store_t4(sXT, m, q, v);
    }
    const float invS = 1.f / (float)S_;
    for (int idx = tid; idx < TILE * 25; idx += NTHR) {
        int m = idx / 25, q = idx - m * 25;
        const int* np = sNI + m * S_;
        float ax = 0.f, ay = 0.f, az = 0.f, aw = 0.f;
#pragma unroll
        for (int s = 0; s < S_; s++) {
            float4 v = e4[(size_t)np[s] * 25 + q];
            ax += v.x; ay += v.y; az += v.z; aw += v.w;
        }
        float4 r; r.x = ax * invS; r.y = ay * invS; r.z = az * invS; r.w = aw * invS;
        store_t4(sNT, m, q, r);
    }
    __syncthreads();

    float* outRow0 = outbuf + (size_t)g * GSTRIDE + (size_t)(out_off + row0) * D_;
    gemm_relu_store(sXT, sNT,
                    Wself + (size_t)(g * 4) * 5000, Wneigh + (size_t)(g * 4) * 5000,
                    bself + (size_t)(g * 4) * DH_,  bneigh + (size_t)(g * 4) * DH_,
                    outRow0, tid);
}

__global__ __launch_bounds__(NTHR, 3)
void pass0_fused(const float* __restrict__ emb,
                 const int* __restrict__ nodeids, const int* __restrict__ n0,
                 const int* __restrict__ n1, const int* __restrict__ n2,
                 const int* __restrict__ n3,
                 const float* __restrict__ Ws, const float* __restrict__ Wn,
                 const float* __restrict__ bs, const float* __restrict__ bn,
                 float* __restrict__ outbuf)
{
    const int bx = blockIdx.x, g = blockIdx.y;
    if      (bx < 840) pass0_body<9>(emb, n2, 53760, n3, 483840, Ws, Wn, bs, bn, outbuf, 9728, bx,       g);
    else if (bx < 960) pass0_body<7>(emb, n1, 7680,  n2, 53760,  Ws, Wn, bs, bn, outbuf, 2048, bx - 840, g);
    else if (bx < 984) pass0_body<5>(emb, n0, 1536,  n1, 7680,   Ws, Wn, bs, bn, outbuf, 512,  bx - 960, g);
    else               pass0_body<3>(emb, nodeids, 0, n0, 1536,  Ws, Wn, bs, bn, outbuf, 0,    bx - 984, g);
}

#define SMEM0 ((2 * D_ * STP + 16 + TILE + TILE * 9) * 4)

// ================= merged tail: passes 1-3 + FC + attention =================
#define GSZ    4064
#define CMB    (3 * GSZ)        // 12192
#define C_SPEC 0
#define C_QN   304
#define C_QS   408
#define C_KS   512
#define C_VS   816
#define C_CTX  1120
#define C_SEL  1224
#define C_TMP  1328
#define C_RED  1536
#define C_RES  1552
#define C_SC   1556
#define TAIL_SMEM ((CMB + 1568) * 4)

__device__ __forceinline__ float bsum384(float v, float* red, int tid) {
    __syncthreads();
#pragma unroll
    for (int o = 16; o; o >>= 1) v += __shfl_xor_sync(0xffffffffu, v, o);
    if ((tid & 31) == 0) red[tid >> 5] = v;
    __syncthreads();
    if (tid == 0) {
        float s = 0.f;
#pragma unroll
        for (int w = 0; w < 12; w++) s += red[w];
        red[0] = s;
    }
    __syncthreads();
    return red[0];
}

__global__ __launch_bounds__(384, 3)
void tail_attn_kernel(const float* __restrict__ bufA,
                      const float* __restrict__ Wself, const float* __restrict__ Wneigh,
                      const float* __restrict__ bself, const float* __restrict__ bneigh,
                      const float* __restrict__ Wfc, const float* __restrict__ bfc,
                      const int* __restrict__ nodeids, const int* __restrict__ edgetypes,
                      const float* __restrict__ base,
                      const float* __restrict__ lng, const float* __restrict__ lnb,
                      const float* __restrict__ Wq, const float* __restrict__ Wk,
                      const float* __restrict__ Wv, const float* __restrict__ Wo,
                      const float* __restrict__ reflect, float* __restrict__ out)
{
    extern __shared__ float sm[];
    const int b   = blockIdx.x;
    const int tid = threadIdx.x;
    const int g   = tid >> 7;
    const int gl  = tid & 127;

    float* gm  = sm + g * GSZ;
    float* sFT = gm;            // [k][20] self feats; reused for pass1 output
    float* sMT = gm + 2000;     // [k][20] means; later aliased:
    float* sMG = gm + 2000;     //   [k][4]  (alias, used after pass1)
    float* sG2 = gm + 2400;     //   [k][4]
    float* sM3 = gm + 2800;     //   [100]
    float* sG3 = gm + 2904;     //   [104]
    float* cm  = sm + CMB;
    float* spec = cm + C_SPEC;
    float* red  = cm + C_RED;
    float* res  = cm + C_RES;
    float* sc   = cm + C_SC;

    const float* in = bufA + (size_t)g * GSTRIDE;

    // ---- stage self feats transposed ----
    for (int i = gl; i < 1900; i += 128) {
        int r = i / 100, j = i - r * 100;
        int src = (r == 0) ? b : (r < 4) ? 512 + 3 * b + (r - 1) : 2048 + 15 * b + (r - 4);
        sFT[j * 20 + r] = in[(size_t)src * 100 + j];
    }
    // ---- f3 group means ----
    for (int i = gl; i < 1500; i += 128) {
        int r = i / 100, j = i - r * 100;
        const float* p = in + (size_t)(9728 + 105 * b + 7 * r) * 100 + j;
        float a = p[0];
#pragma unroll
        for (int s = 1; s < 7; s++) a += p[s * 100];
        sMT[j * 20 + 4 + r] = a * (1.f / 7.f);
    }
    if (gl < 100) { sFT[gl * 20 + 19] = 0.f; sMT[gl * 20 + 19] = 0.f; }
    __syncthreads();
    // ---- mf1, mf2 ----
    for (int i = gl; i < 400; i += 128) {
        int r = i / 100, j = i - r * 100;
        const float* col = sFT + j * 20;
        float a;
        if (r == 0) a = (col[1] + col[2] + col[3]) * (1.f / 3.f);
        else {
            int q = 4 + 5 * (r - 1);
            a = (col[q] + col[q + 1] + col[q + 2] + col[q + 3] + col[q + 4]) * 0.2f;
        }
        sMT[j * 20 + r] = a;
    }
    __syncthreads();

    const bool act   = (gl < 100);
    const bool selfh = (gl < 50);
    const int  jj    = selfh ? gl : gl - 50;

    // ---- pass 1: accumulate in regs (prefetch-5), then write back into sFT ----
    ull acc1[10];
    {
        const float* Wp = (selfh ? Wself : Wneigh) + (size_t)(g * 4 + 1) * 5000 + jj;
        const float* srcp = selfh ? sFT : sMT;
        float bias = act ? (selfh ? bself[(g * 4 + 1) * 50 + jj] : bneigh[(g * 4 + 1) * 50 + jj]) : 0.f;
        ull b2 = pk2(bias, bias);
#pragma unroll
        for (int p = 0; p < 10; p++) acc1[p] = b2;
        if (act) {
#pragma unroll
            for (int k0 = 0; k0 < 100; k0 += 5) {
                float wv[5];
#pragma unroll
                for (int i = 0; i < 5; i++) wv[i] = __ldg(Wp + (k0 + i) * 50);
#pragma unroll
                for (int i = 0; i < 5; i++) {
                    ull w2 = pk2(wv[i], wv[i]);
                    const float4* xr = (const float4*)(srcp + (k0 + i) * 20);
#pragma unroll
                    for (int q = 0; q < 5; q++) {
                        float4 xv = xr[q];
                        FMA2(acc1[2 * q],     pk2(xv.x, xv.y), w2);
                        FMA2(acc1[2 * q + 1], pk2(xv.z, xv.w), w2);
                    }
                }
            }
        }
    }
    __syncthreads();                 // all reads of sFT/sMT complete
    if (act) {
        float* o = sFT + gl * 20;    // sFT now holds G1 [j][r]
#pragma unroll
        for (int p = 0; p < 10; p++) {
            float2 v = upk2(acc1[p]);
            o[2 * p] = fmaxf(v.x, 0.f);
            if (2 * p + 1 < 19) o[2 * p + 1] = fmaxf(v.y, 0.f);
        }
        o[19] = 0.f;
    }
    __syncthreads();

    // ---- pass 2 means -> sMG ----
    if (act) {
        const float* col = sFT + gl * 20;
        float* mg = sMG + gl * 4;
        mg[0] = (col[1] + col[2] + col[3]) * (1.f / 3.f);
#pragma unroll
        for (int r = 0; r < 3; r++) {
            int q = 4 + 5 * r;
            mg[1 + r] = (col[q] + col[q + 1] + col[q + 2] + col[q + 3] + col[q + 4]) * 0.2f;
        }
    }
    __syncthreads();

    // ---- pass 2: 4 rows (prefetch-10) ----
    {
        const float* Wp = (selfh ? Wself : Wneigh) + (size_t)(g * 4 + 2) * 5000 + jj;
        const float* srcp = selfh ? sFT : sMG;
        const int pitch = selfh ? 20 : 4;
        float bias = act ? (selfh ? bself[(g * 4 + 2) * 50 + jj] : bneigh[(g * 4 + 2) * 50 + jj]) : 0.f;
        ull a0 = pk2(bias, bias), a1 = a0;
        if (act) {
#pragma unroll
            for (int k0 = 0; k0 < 100; k0 += 10) {
                float wv[10];
#pragma unroll
                for (int i = 0; i < 10; i++) wv[i] = __ldg(Wp + (k0 + i) * 50);
#pragma unroll
                for (int i = 0; i < 10; i++) {
                    ull w2 = pk2(wv[i], wv[i]);
                    float4 xv = *(const float4*)(srcp + (k0 + i) * pitch);
                    FMA2(a0, pk2(xv.x, xv.y), w2);
                    FMA2(a1, pk2(xv.z, xv.w), w2);
                }
            }
            float* o = sG2 + gl * 4;
            float2 v0 = upk2(a0), v1 = upk2(a1);
            o[0] = fmaxf(v0.x, 0.f); o[1] = fmaxf(v0.y, 0.f);
            o[2] = fmaxf(v1.x, 0.f); o[3] = fmaxf(v1.y, 0.f);
        }
    }
    __syncthreads();

    if (act)
        sM3[gl] = (sG2[gl * 4 + 1] + sG2[gl * 4 + 2] + sG2[gl * 4 + 3]) * (1.f / 3.f);
    __syncthreads();

    // ---- pass 3 (prefetch-10) + per-group l2norm ----
    float g3 = 0.f;
    if (act) {
        const float* Wp = (selfh ? Wself : Wneigh) + (size_t)(g * 4 + 3) * 5000 + jj;
        float a = selfh ? bself[(g * 4 + 3) * 50 + jj] : bneigh[(g * 4 + 3) * 50 + jj];
#pragma unroll
        for (int k0 = 0; k0 < 100; k0 += 10) {
            float wv[10];
#pragma unroll
            for (int i = 0; i < 10; i++) wv[i] = __ldg(Wp + (k0 + i) * 50);
#pragma unroll
            for (int i = 0; i < 10; i++) {
                float x = selfh ? sG2[(k0 + i) * 4] : sM3[k0 + i];
                a += x * wv[i];
            }
        }
        g3 = fmaxf(a, 0.f);
        sG3[gl] = g3;
    }
    {
        float v = act ? g3 * g3 : 0.f;
#pragma unroll
        for (int o = 16; o; o >>= 1) v += __shfl_xor_sync(0xffffffffu, v, o);
        if ((tid & 31) == 0) red[tid >> 5] = v;
        __syncthreads();
        if (gl == 0) {
            float s = red[4 * g] + red[4 * g + 1] + red[4 * g + 2] + red[4 * g + 3];
            res[g] = 1.f / fmaxf(sqrtf(s), 1e-12f);
        }
        __syncthreads();
    }

    // ---- FC -> spec[g] (prefetch-10) ----
    if (act) {
        const float* Wf = Wfc + (size_t)g * 10000 + gl;
        float a = 0.f;
#pragma unroll
        for (int k0 = 0; k0 < 100; k0 += 10) {
            float wv[10];
#pragma unroll
            for (int i = 0; i < 10; i++) wv[i] = __ldg(Wf + (k0 + i) * 100);
#pragma unroll
            for (int i = 0; i < 10; i++) a += sG3[k0 + i] * wv[i];
        }
        spec[g * 100 + gl] = a * res[g] + bfc[g * 100 + gl];
    }
    __syncthreads();

    // ================= attention + reflect =================
    float* qn  = cm + C_QN;
    float* Qs  = cm + C_QS;
    float* Ks  = cm + C_KS;
    float* Vs  = cm + C_VS;
    float* ctx = cm + C_CTX;
    float* sel = cm + C_SEL;
    float* tmp = cm + C_TMP;

    const int et = edgetypes[b];

    float x = (tid < 100) ? spec[et * 100 + tid] : 0.f;
    float mu = bsum384(x, red, tid) * 0.01f;
    float dd = (tid < 100) ? (x - mu) : 0.f;
    float var = bsum384(dd * dd, red, tid) * 0.01f;
    if (tid < 100) qn[tid] = dd * rsqrtf(var + 1e-6f) * lng[tid] + lnb[tid];
    __syncthreads();

    if (tid < 100) {
        float aq = 0.f;
#pragma unroll
        for (int k0 = 0; k0 < 100; k0 += 10) {
            float wv[10];
#pragma unroll
            for (int i = 0; i < 10; i++) wv[i] = __ldg(Wq + (k0 + i) * 100 + tid);
#pragma unroll
            for (int i = 0; i < 10; i++) aq += qn[k0 + i] * wv[i];
        }
        Qs[tid] = aq;
    }
    if (tid < 300) {
        int h = tid / 100, j = tid - h * 100;
        const float* sp = spec + h * 100;
        float ak = 0.f, av = 0.f;
#pragma unroll
        for (int k0 = 0; k0 < 100; k0 += 10) {
            float wk[10], wv[10];
#pragma unroll
            for (int i = 0; i < 10; i++) {
                wk[i] = __ldg(Wk + (k0 + i) * 100 + j);
                wv[i] = __ldg(Wv + (k0 + i) * 100 + j);
            }
#pragma unroll
            for (int i = 0; i < 10; i++) {
                float s = sp[k0 + i];
                ak += s * wk[i];
                av += s * wv[i];
            }
        }
        Ks[h * 100 + j] = ak;
        Vs[h * 100 + j] = av;
    }
    __syncthreads();

    for (int h = 0; h < 3; h++) {
        float p = (tid < 100) ? Qs[tid] * Ks[h * 100 + tid] : 0.f;
        float s = bsum384(p, red, tid);
        if (tid == 0) sc[h] = s * 0.1f;
    }
    __syncthreads();
    {
        float m = fmaxf(sc[0], fmaxf(sc[1], sc[2]));
        float e0 = expf(sc[0] - m), e1 = expf(sc[1] - m), e2 = expf(sc[2] - m);
        float inv = 1.f / (e0 + e1 + e2);
        float a0 = e0 * inv, a1 = e1 * inv, a2 = e2 * inv;
        if (tid < 100)
            ctx[tid] = a0 * Vs[tid] + a1 * Vs[100 + tid] + a2 * Vs[200 + tid];
    }
    __syncthreads();
    if (tid < 100) {
        float a = spec[et * 100 + tid];
#pragma unroll
        for (int k0 = 0; k0 < 100; k0 += 10) {
            float wv[10];
#pragma unroll
            for (int i = 0; i < 10; i++) wv[i] = __ldg(Wo + (k0 + i) * 100 + tid);
#pragma unroll
            for (int i = 0; i < 10; i++) a += ctx[k0 + i] * wv[i];
        }
        sel[tid] = a;
    }
    __syncthreads();

    const int nid = nodeids[b];
    const float* R = reflect + (size_t)et * 100 * DIN_;
    float lss = 0.f;
    if (tid < DIN_) {
        float a = 0.f;
#pragma unroll
        for (int k0 = 0; k0 < 100; k0 += 10) {
            float wv[10];
#pragma unroll
            for (int i = 0; i < 10; i++) wv[i] = __ldg(R + (k0 + i) * DIN_ + tid);
#pragma unroll
            for (int i = 0; i < 10; i++) a += sel[k0 + i] * wv[i];
        }
        float r = base[(size_t)nid * DIN_ + tid] + a;
        tmp[tid] = r;
        lss = r * r;
    }
    float ss = bsum384(lss, red, tid);
    float sca = 1.f / fmaxf(sqrtf(ss), 1e-12f);
    if (tid < DIN_) out[(size_t)b * DIN_ + tid] = tmp[tid] * sca;
}

extern "C" void kernel_launch(void* const* d_in, const int* in_sizes, int n_in,
                              void* d_out, int out_size) {
    const int*   nodeids   = (const int*)d_in[0];
    const int*   edgetypes = (const int*)d_in[1];
    const int*   n0        = (const int*)d_in[2];
    const int*   n1        = (const int*)d_in[3];
    const int*   n2        = (const int*)d_in[4];
    const int*   n3        = (const int*)d_in[5];
    const float* base      = (const float*)d_in[6];
    const float* emb       = (const float*)d_in[7];
    const float* Wself     = (const float*)d_in[8];
    const float* bself     = (const float*)d_in[9];
    const float* Wneigh    = (const float*)d_in[10];
    const float* bneigh    = (const float*)d_in[11];
    const float* Wfc       = (const float*)d_in[12];
    const float* bfc       = (const float*)d_in[13];
    const float* lng       = (const float*)d_in[14];
    const float* lnb       = (const float*)d_in[15];
    const float* Wq        = (const float*)d_in[16];
    const float* Wk        = (const float*)d_in[17];
    const float* Wv        = (const float*)d_in[18];
    const float* Wo        = (const float*)d_in[19];
    const float* reflect   = (const float*)d_in[20];
    float* out = (float*)d_out;

    float *bufA;
    cudaGetSymbolAddress((void**)&bufA, g_bufA);

    cudaFuncSetAttribute(pass0_fused, cudaFuncAttributeMaxDynamicSharedMemorySize, SMEM0);
    cudaFuncSetAttribute(tail_attn_kernel, cudaFuncAttributeMaxDynamicSharedMemorySize, TAIL_SMEM);

    pass0_fused<<<dim3(992, 3), NTHR, SMEM0>>>(emb, nodeids, n0, n1, n2, n3,
                                               Wself, Wneigh, bself, bneigh, bufA);
    tail_attn_kernel<<<B_, 384, TAIL_SMEM>>>(bufA, Wself, Wneigh, bself, bneigh, Wfc, bfc,
                                             nodeids, edgetypes, base, lng, lnb,
                                             Wq, Wk, Wv, Wo, reflect, out);
}

// round 7
// speedup vs baseline: 1.8896x; 1.0359x over previous
#include <cuda_runtime.h>
#include <math.h>

#define D_      100
#define DH_     50
#define B_      512
#define G_      3
#define NTAB    100000
#define DIN_    200
#define STP     132          // tile pitch: [k][STP], cols 0..123 used (swizzled)

__device__ float g_spec[B_ * G_ * D_];

typedef unsigned long long ull;

__device__ __forceinline__ ull pk2(float lo, float hi) {
    ull r; asm("mov.b64 %0, {%1, %2};" : "=l"(r) : "f"(lo), "f"(hi)); return r;
}
__device__ __forceinline__ float2 upk2(ull v) {
    float2 f; asm("mov.b64 {%0, %1}, %2;" : "=f"(f.x), "=f"(f.y) : "l"(v)); return f;
}
#define FMA2(acc, a, b) asm("fma.rn.f32x2 %0, %1, %2, %0;" : "+l"(acc) : "l"(a), "l"(b))

// transposed+swizzled tile store: element (k=4q+d, col m) at sT[k*STP + (m ^ 2*(k>>4))]
__device__ __forceinline__ void store_t4(float* sT, int m, int q, float4 v) {
    int col = m ^ (2 * (q >> 2));
    int k = q * 4;
    sT[(k + 0) * STP + col] = v.x;
    sT[(k + 1) * STP + col] = v.y;
    sT[(k + 2) * STP + col] = v.z;
    sT[(k + 3) * STP + col] = v.w;
}

__device__ __forceinline__ float bsum384(float v, float* red, int tid) {
    __syncthreads();
#pragma unroll
    for (int o = 16; o; o >>= 1) v += __shfl_xor_sync(0xffffffffu, v, o);
    if ((tid & 31) == 0) red[tid >> 5] = v;
    __syncthreads();
    if (tid == 0) {
        float s = 0.f;
#pragma unroll
        for (int w = 0; w < 12; w++) s += red[w];
        red[0] = s;
    }
    __syncthreads();
    return red[0];
}

// ===================== fused GraphSage: one block per (b,g) =====================
// smem: sA 100*132 (self feats -> g0 [124][100]) | sM 100*132 (means -> tail bufs)
//       sIdx 1072 ints | red 16
#define SM_A    0
#define SM_M    13200
#define SM_IDX  26400
#define SM_RED  27480
#define FUSED_SMEM ((27480 + 16) * 4)

__global__ __launch_bounds__(384, 2)
void fused_sage(const float* __restrict__ emb,
                const int* __restrict__ nodeids,
                const int* __restrict__ n0, const int* __restrict__ n1,
                const int* __restrict__ n2, const int* __restrict__ n3,
                const float* __restrict__ Wself, const float* __restrict__ Wneigh,
                const float* __restrict__ bself, const float* __restrict__ bneigh,
                const float* __restrict__ Wfc, const float* __restrict__ bfc,
                float* __restrict__ spec_out)
{
    extern __shared__ float sm[];
    float* sA   = sm + SM_A;
    float* sMn  = sm + SM_M;
    int*   sIdx = (int*)(sm + SM_IDX);
    float* red  = sm + SM_RED;

    const int b = blockIdx.x, g = blockIdx.y, tid = threadIdx.x;

    // ---- indices: [0]=seed, [1..3]=n0, [4..18]=n1, [19..123]=n2, [124..1068]=n3 ----
    if (tid == 0)  sIdx[0] = nodeids[b];
    if (tid < 3)   sIdx[1 + tid]  = n0[g * 1536  + 3 * b   + tid];
    if (tid < 15)  sIdx[4 + tid]  = n1[g * 7680  + 15 * b  + tid];
    if (tid < 105) sIdx[19 + tid] = n2[g * 53760 + 105 * b + tid];
    for (int i = tid; i < 945; i += 384) sIdx[124 + i] = n3[(size_t)g * 483840 + 945 * b + i];
    __syncthreads();

    const float4* e4 = (const float4*)(emb + (size_t)g * NTAB * D_);

    // ---- self gather: 124 rows -> sA ----
    for (int idx = tid; idx < 124 * 25; idx += 384) {
        int m = idx / 25, q = idx - m * 25;
        float4 v = e4[(size_t)sIdx[m] * 25 + q];
        store_t4(sA, m, q, v);
    }
    // ---- neighbor means -> sMn (4 levels, constant group size each) ----
    for (int idx = tid; idx < 25; idx += 384) {          // r=0: mean of n0 (S=3)
        int q = idx;
        float4 a = e4[(size_t)sIdx[1] * 25 + q];
        float4 v1 = e4[(size_t)sIdx[2] * 25 + q];
        float4 v2 = e4[(size_t)sIdx[3] * 25 + q];
        a.x = (a.x + v1.x + v2.x) * (1.f / 3.f);
        a.y = (a.y + v1.y + v2.y) * (1.f / 3.f);
        a.z = (a.z + v1.z + v2.z) * (1.f / 3.f);
        a.w = (a.w + v1.w + v2.w) * (1.f / 3.f);
        store_t4(sMn, 0, q, a);
    }
    for (int idx = tid; idx < 3 * 25; idx += 384) {      // r=1..3: groups of 5 (n1)
        int r = idx / 25, q = idx - r * 25;
        const int* np = sIdx + 4 + 5 * r;
        float ax = 0, ay = 0, az = 0, aw = 0;
#pragma unroll
        for (int s = 0; s < 5; s++) {
            float4 v = e4[(size_t)np[s] * 25 + q];
            ax += v.x; ay += v.y; az += v.z; aw += v.w;
        }
        float4 o; o.x = ax * 0.2f; o.y = ay * 0.2f; o.z = az * 0.2f; o.w = aw * 0.2f;
        store_t4(sMn, 1 + r, q, o);
    }
    for (int idx = tid; idx < 15 * 25; idx += 384) {     // r=4..18: groups of 7 (n2)
        int r = idx / 25, q = idx - r * 25;
        const int* np = sIdx + 19 + 7 * r;
        float ax = 0, ay = 0, az = 0, aw = 0;
#pragma unroll
        for (int s = 0; s < 7; s++) {
            float4 v = e4[(size_t)np[s] * 25 + q];
            ax += v.x; ay += v.y; az += v.z; aw += v.w;
        }
        const float c = 1.f / 7.f;
        float4 o; o.x = ax * c; o.y = ay * c; o.z = az * c; o.w = aw * c;
        store_t4(sMn, 4 + r, q, o);
    }
    for (int idx = tid; idx < 105 * 25; idx += 384) {    // r=19..123: groups of 9 (n3)
        int r = idx / 25, q = idx - r * 25;
        const int* np = sIdx + 124 + 9 * r;
        float ax = 0, ay = 0, az = 0, aw = 0;
#pragma unroll
        for (int s = 0; s < 9; s++) {
            float4 v = e4[(size_t)np[s] * 25 + q];
            ax += v.x; ay += v.y; az += v.z; aw += v.w;
        }
        const float c = 1.f / 9.f;
        float4 o; o.x = ax * c; o.y = ay * c; o.z = az * c; o.w = aw * c;
        store_t4(sMn, 19 + r, q, o);
    }
    __syncthreads();

    // ---- pass 0 GEMM: out[124][100], 350 threads, acc in regs ----
    ull acc[9][2];
    int j0 = 0, mr = 0;
    if (tid < 350) {
        const int ct = tid % 50, rt = tid / 50;
        j0 = 2 * ct; mr = rt * 18;
        const bool selfh = (j0 < DH_);
        const int jj = selfh ? j0 : j0 - DH_;
        const float* aT = selfh ? sA : sMn;
        const float* Wp = (selfh ? Wself : Wneigh) + (size_t)(g * 4) * 5000 + jj;
        const float* bp = (selfh ? bself : bneigh) + (g * 4) * DH_;
        {
            float b0 = bp[jj], b1 = bp[jj + 1];
            ull bb0 = pk2(b0, b0), bb1 = pk2(b1, b1);
#pragma unroll
            for (int p = 0; p < 9; p++) { acc[p][0] = bb0; acc[p][1] = bb1; }
        }
#pragma unroll
        for (int kb = 0; kb < 7; kb++) {
            const int sw = 2 * kb;
            const int kmax = (kb == 6) ? 4 : 16;
#pragma unroll
            for (int kk = 0; kk < kmax; kk += 4) {
                float2 wv[4];
#pragma unroll
                for (int i = 0; i < 4; i++)
                    wv[i] = __ldg((const float2*)(Wp + (kb * 16 + kk + i) * DH_));
#pragma unroll
                for (int i = 0; i < 4; i++) {
                    const float* ak = aT + (kb * 16 + kk + i) * STP;
                    ull wd0 = pk2(wv[i].x, wv[i].x), wd1 = pk2(wv[i].y, wv[i].y);
#pragma unroll
                    for (int p = 0; p < 9; p++) {
                        ull x = *(const ull*)(ak + ((mr + 2 * p) ^ sw));
                        FMA2(acc[p][0], x, wd0);
                        FMA2(acc[p][1], x, wd1);
                    }
                }
            }
        }
    }
    __syncthreads();
    // write g0 [r][100] into sA (plain layout, conflict-free float2 stores)
    if (tid < 350) {
#pragma unroll
        for (int p = 0; p < 9; p++) {
            int r0 = mr + 2 * p, r1 = r0 + 1;
            float2 v0 = upk2(acc[p][0]);   // rows (r0,r1) col j0
            float2 v1 = upk2(acc[p][1]);   // rows (r0,r1) col j0+1
            if (r0 < 124) {
                float2 t; t.x = fmaxf(v0.x, 0.f); t.y = fmaxf(v1.x, 0.f);
                *(float2*)(sA + r0 * 100 + j0) = t;
            }
            if (r1 < 124) {
                float2 t; t.x = fmaxf(v0.y, 0.f); t.y = fmaxf(v1.y, 0.f);
                *(float2*)(sA + r1 * 100 + j0) = t;
            }
        }
    }
    __syncthreads();

    // ---- stage tail buffers into sMn region (dead) ----
    float* sFT = sMn;          // [j][20]: g0 rows 0..18 + pad
    float* sMT = sMn + 2000;   // [j][20]: means (mf1|mf2(3)|f3means(15)|pad)
    float* sMG = sMn + 4000;   // [j][4]
    float* sG2 = sMn + 4400;   // [j][4]
    float* sM3 = sMn + 4816;   // [100]
    float* sG3 = sMn + 4920;   // [104]

    for (int i = tid; i < 1900; i += 384) {
        int r = i / 100, j = i - r * 100;
        sFT[j * 20 + r] = sA[r * 100 + j];
    }
    for (int i = tid; i < 1500; i += 384) {
        int r = i / 100, j = i - r * 100;
        const float* p = sA + (19 + 7 * r) * 100 + j;
        float a = p[0];
#pragma unroll
        for (int s = 1; s < 7; s++) a += p[s * 100];
        sMT[j * 20 + 4 + r] = a * (1.f / 7.f);
    }
    if (tid < 100) { sFT[tid * 20 + 19] = 0.f; sMT[tid * 20 + 19] = 0.f; }
    __syncthreads();
    for (int i = tid; i < 400; i += 384) {
        int r = i / 100, j = i - r * 100;
        const float* col = sFT + j * 20;
        float a;
        if (r == 0) a = (col[1] + col[2] + col[3]) * (1.f / 3.f);
        else {
            int q = 4 + 5 * (r - 1);
            a = (col[q] + col[q + 1] + col[q + 2] + col[q + 3] + col[q + 4]) * 0.2f;
        }
        sMT[j * 20 + r] = a;
    }
    __syncthreads();

    const bool act   = (tid < 100);
    const bool selfh = (tid < 50);
    const int  jj    = selfh ? tid : tid - 50;

    // ---- pass 1: 19 rows (10 pairs) in regs -> write back to sFT ----
    ull acc1[10];
    {
        const float* Wp = (selfh ? Wself : Wneigh) + (size_t)(g * 4 + 1) * 5000 + jj;
        const float* srcp = selfh ? sFT : sMT;
        float bias = act ? (selfh ? bself[(g * 4 + 1) * 50 + jj] : bneigh[(g * 4 + 1) * 50 + jj]) : 0.f;
        ull b2 = pk2(bias, bias);
#pragma unroll
        for (int p = 0; p < 10; p++) acc1[p] = b2;
        if (act) {
#pragma unroll
            for (int k0 = 0; k0 < 100; k0 += 5) {
                float wv[5];
#pragma unroll
                for (int i = 0; i < 5; i++) wv[i] = __ldg(Wp + (k0 + i) * 50);
#pragma unroll
                for (int i = 0; i < 5; i++) {
                    ull w2 = pk2(wv[i], wv[i]);
                    const float4* xr = (const float4*)(srcp + (k0 + i) * 20);
#pragma unroll
                    for (int q = 0; q < 5; q++) {
                        float4 xv = xr[q];
                        FMA2(acc1[2 * q],     pk2(xv.x, xv.y), w2);
                        FMA2(acc1[2 * q + 1], pk2(xv.z, xv.w), w2);
                    }
                }
            }
        }
    }
    __syncthreads();
    if (act) {
        float* o = sFT + tid * 20;
#pragma unroll
        for (int p = 0; p < 10; p++) {
            float2 v = upk2(acc1[p]);
            o[2 * p] = fmaxf(v.x, 0.f);
            if (2 * p + 1 < 19) o[2 * p + 1] = fmaxf(v.y, 0.f);
        }
        o[19] = 0.f;
    }
    __syncthreads();

    // ---- pass 2 means ----
    if (act) {
        const float* col = sFT + tid * 20;
        float* mg = sMG + tid * 4;
        mg[0] = (col[1] + col[2] + col[3]) * (1.f / 3.f);
#pragma unroll
        for (int r = 0; r < 3; r++) {
            int q = 4 + 5 * r;
            mg[1 + r] = (col[q] + col[q + 1] + col[q + 2] + col[q + 3] + col[q + 4]) * 0.2f;
        }
    }
    __syncthreads();

    // ---- pass 2: 4 rows ----
    {
        const float* Wp = (selfh ? Wself : Wneigh) + (size_t)(g * 4 + 2) * 5000 + jj;
        const float* srcp = selfh ? sFT : sMG;
        const int pitch = selfh ? 20 : 4;
        float bias = act ? (selfh ? bself[(g * 4 + 2) * 50 + jj] : bneigh[(g * 4 + 2) * 50 + jj]) : 0.f;
        ull a0 = pk2(bias, bias), a1 = a0;
        if (act) {
#pragma unroll
            for (int k0 = 0; k0 < 100; k0 += 10) {
                float wv[10];
#pragma unroll
                for (int i = 0; i < 10; i++) wv[i] = __ldg(Wp + (k0 + i) * 50);
#pragma unroll
                for (int i = 0; i < 10; i++) {
                    ull w2 = pk2(wv[i], wv[i]);
                    float4 xv = *(const float4*)(srcp + (k0 + i) * pitch);
                    FMA2(a0, pk2(xv.x, xv.y), w2);
                    FMA2(a1, pk2(xv.z, xv.w), w2);
                }
            }
            float* o = sG2 + tid * 4;
            float2 v0 = upk2(a0), v1 = upk2(a1);
            o[0] = fmaxf(v0.x, 0.f); o[1] = fmaxf(v0.y, 0.f);
            o[2] = fmaxf(v1.x, 0.f); o[3] = fmaxf(v1.y, 0.f);
        }
    }
    __syncthreads();

    if (act)
        sM3[tid] = (sG2[tid * 4 + 1] + sG2[tid * 4 + 2] + sG2[tid * 4 + 3]) * (1.f / 3.f);
    __syncthreads();

    // ---- pass 3 + l2norm ----
    float g3 = 0.f;
    if (act) {
        const float* Wp = (selfh ? Wself : Wneigh) + (size_t)(g * 4 + 3) * 5000 + jj;
        float a = selfh ? bself[(g * 4 + 3) * 50 + jj] : bneigh[(g * 4 + 3) * 50 + jj];
#pragma unroll
        for (int k0 = 0; k0 < 100; k0 += 10) {
            float wv[10];
#pragma unroll
            for (int i = 0; i < 10; i++) wv[i] = __ldg(Wp + (k0 + i) * 50);
#pragma unroll
            for (int i = 0; i < 10; i++) {
                float x = selfh ? sG2[(k0 + i) * 4] : sM3[k0 + i];
                a += x * wv[i];
            }
        }
        g3 = fmaxf(a, 0.f);
        sG3[tid] = g3;
    }
    float ss = bsum384(act ? g3 * g3 : 0.f, red, tid);
    float s_inv = 1.f / fmaxf(sqrtf(ss), 1e-12f);

    // ---- FC -> spec ----
    if (act) {
        const float* Wf = Wfc + (size_t)g * 10000 + tid;
        float a = 0.f;
#pragma unroll
        for (int k0 = 0; k0 < 100; k0 += 10) {
            float wv[10];
#pragma unroll
            for (int i = 0; i < 10; i++) wv[i] = __ldg(Wf + (k0 + i) * 100);
#pragma unroll
            for (int i = 0; i < 10; i++) a += sG3[k0 + i] * wv[i];
        }
        spec_out[(size_t)(b * 3 + g) * 100 + tid] = a * s_inv + bfc[g * 100 + tid];
    }
}

// ===================== attention + reflect, one block per seed =====================
__global__ __launch_bounds__(384)
void attn_kernel(const float* __restrict__ spec_in,
                 const int* __restrict__ nodeids, const int* __restrict__ edgetypes,
                 const float* __restrict__ base,
                 const float* __restrict__ lng, const float* __restrict__ lnb,
                 const float* __restrict__ Wq, const float* __restrict__ Wk,
                 const float* __restrict__ Wv, const float* __restrict__ Wo,
                 const float* __restrict__ reflect, float* __restrict__ out)
{
    __shared__ float spec[300];
    __shared__ float qn[100], Qs[100], Ks[300], Vs[300], ctx[100], sel[100];
    __shared__ float tmp[DIN_];
    __shared__ float red[12], sc[3];

    const int b = blockIdx.x, tid = threadIdx.x;

    for (int i = tid; i < 300; i += 384) spec[i] = spec_in[(size_t)b * 300 + i];
    __syncthreads();

    const int et = edgetypes[b];

    float x = (tid < 100) ? spec[et * 100 + tid] : 0.f;
    float mu = bsum384(x, red, tid) * 0.01f;
    float dd = (tid < 100) ? (x - mu) : 0.f;
    float var = bsum384(dd * dd, red, tid) * 0.01f;
    if (tid < 100) qn[tid] = dd * rsqrtf(var + 1e-6f) * lng[tid] + lnb[tid];
    __syncthreads();

    if (tid < 100) {
        float aq = 0.f;
#pragma unroll
        for (int k0 = 0; k0 < 100; k0 += 10) {
            float wv[10];
#pragma unroll
            for (int i = 0; i < 10; i++) wv[i] = __ldg(Wq + (k0 + i) * 100 + tid);
#pragma unroll
            for (int i = 0; i < 10; i++) aq += qn[k0 + i] * wv[i];
        }
        Qs[tid] = aq;
    }
    if (tid < 300) {
        int h = tid / 100, j = tid - h * 100;
        const float* sp = spec + h * 100;
        float ak = 0.f, av = 0.f;
#pragma unroll
        for (int k0 = 0; k0 < 100; k0 += 10) {
            float wk[10], wv[10];
#pragma unroll
            for (int i = 0; i < 10; i++) {
                wk[i] = __ldg(Wk + (k0 + i) * 100 + j);
                wv[i] = __ldg(Wv + (k0 + i) * 100 + j);
            }
#pragma unroll
            for (int i = 0; i < 10; i++) {
                float s = sp[k0 + i];
                ak += s * wk[i];
                av += s * wv[i];
            }
        }
        Ks[h * 100 + j] = ak;
        Vs[h * 100 + j] = av;
    }
    __syncthreads();

    for (int h = 0; h < 3; h++) {
        float p = (tid < 100) ? Qs[tid] * Ks[h * 100 + tid] : 0.f;
        float s = bsum384(p, red, tid);
        if (tid == 0) sc[h] = s * 0.1f;
    }
    __syncthreads();
    {
        float m = fmaxf(sc[0], fmaxf(sc[1], sc[2]));
        float e0 = expf(sc[0] - m), e1 = expf(sc[1] - m), e2 = expf(sc[2] - m);
        float inv = 1.f / (e0 + e1 + e2);
        float a0 = e0 * inv, a1 = e1 * inv, a2 = e2 * inv;
        if (tid < 100)
            ctx[tid] = a0 * Vs[tid] + a1 * Vs[100 + tid] + a2 * Vs[200 + tid];
    }
    __syncthreads();
    if (tid < 100) {
        float a = spec[et * 100 + tid];
#pragma unroll
        for (int k0 = 0; k0 < 100; k0 += 10) {
            float wv[10];
#pragma unroll
            for (int i = 0; i < 10; i++) wv[i] = __ldg(Wo + (k0 + i) * 100 + tid);
#pragma unroll
            for (int i = 0; i < 10; i++) a += ctx[k0 + i] * wv[i];
        }
        sel[tid] = a;
    }
    __syncthreads();

    const int nid = nodeids[b];
    const float* R = reflect + (size_t)et * 100 * DIN_;
    float lss = 0.f;
    if (tid < DIN_) {
        float a = 0.f;
#pragma unroll
        for (int k0 = 0; k0 < 100; k0 += 10) {
            float wv[10];
#pragma unroll
            for (int i = 0; i < 10; i++) wv[i] = __ldg(R + (k0 + i) * DIN_ + tid);
#pragma unroll
            for (int i = 0; i < 10; i++) a += sel[k0 + i] * wv[i];
        }
        float r = base[(size_t)nid * DIN_ + tid] + a;
        tmp[tid] = r;
        lss = r * r;
    }
    float ss = bsum384(lss, red, tid);
    float sca = 1.f / fmaxf(sqrtf(ss), 1e-12f);
    if (tid < DIN_) out[(size_t)b * DIN_ + tid] = tmp[tid] * sca;
}

extern "C" void kernel_launch(void* const* d_in, const int* in_sizes, int n_in,
                              void* d_out, int out_size) {
    const int*   nodeids   = (const int*)d_in[0];
    const int*   edgetypes = (const int*)d_in[1];
    const int*   n0        = (const int*)d_in[2];
    const int*   n1        = (const int*)d_in[3];
    const int*   n2        = (const int*)d_in[4];
    const int*   n3        = (const int*)d_in[5];
    const float* base      = (const float*)d_in[6];
    const float* emb       = (const float*)d_in[7];
    const float* Wself     = (const float*)d_in[8];
    const float* bself     = (const float*)d_in[9];
    const float* Wneigh    = (const float*)d_in[10];
    const float* bneigh    = (const float*)d_in[11];
    const float* Wfc       = (const float*)d_in[12];
    const float* bfc       = (const float*)d_in[13];
    const float* lng       = (const float*)d_in[14];
    const float* lnb       = (const float*)d_in[15];
    const float* Wq        = (const float*)d_in[16];
    const float* Wk        = (const float*)d_in[17];
    const float* Wv        = (const float*)d_in[18];
    const float* Wo        = (const float*)d_in[19];
    const float* reflect   = (const float*)d_in[20];
    float* out = (float*)d_out;

    float* spec;
    cudaGetSymbolAddress((void**)&spec, g_spec);

    cudaFuncSetAttribute(fused_sage, cudaFuncAttributeMaxDynamicSharedMemorySize, FUSED_SMEM);

    fused_sage<<<dim3(B_, G_), 384, FUSED_SMEM>>>(emb, nodeids, n0, n1, n2, n3,
                                                  Wself, Wneigh, bself, bneigh,
                                                  Wfc, bfc, spec);
    attn_kernel<<<B_, 384>>>(spec, nodeids, edgetypes, base, lng, lnb,
                             Wq, Wk, Wv, Wo, reflect, out);
}